// round 11
// baseline (speedup 1.0000x reference)
#include <cuda_runtime.h>
#include <math.h>

// Problem constants
#define Lq   700
#define Bq   32
#define DIN  41
#define Hh   800
#define Gg   3200      // 4*H
#define H2   1600      // 2*H
#define Mq   22400     // L*B
#define KP   48        // padded K for layer-0 input projection

#define RBLK 100       // persistent recurrence blocks (all co-resident: 100 <= 148 SMs)
#define DBLK 50        // blocks 0..49 dir0, 50..99 dir1; 50 blocks * 16 j = 800 exact

// ---------------- device scratch (static; no runtime allocation) ----------------
__device__ __align__(16) float g_xp  [(size_t)2*Lq*Gg*Bq];  // gate preacts [dir][t][n][b]
__device__ __align__(16) float g_ct  [(size_t)2*Mq*Gg];     // GEMM out [dir][m][n]
__device__ __align__(16) float g_h0  [(size_t)Mq*H2];       // layer-0 hidden [t][b][1600]
__device__ __align__(16) float g_h1  [(size_t)Mq*H2];       // layer-1 hidden
__device__ __align__(16) float g_hbuf[2*2*Hh*Bq];           // ping-pong h [buf][dir][k/4][b][4]
__device__ __align__(16) float g_xpad[(size_t)Mq*KP];       // padded x  [m=t*32+b][48]
__device__ __align__(16) float g_wpad[(size_t)2*Gg*KP];     // padded w_ih_l0
__device__ float g_bias[2*Gg];
__device__ float g_logits[(size_t)Mq*20];
__device__ float g_ang[(size_t)Lq*Bq*3];    // angles in NATURAL [l][b][jj] order; the NeRF
                                            // scan reads this flat as [2100][32] — this IS the
                                            // reference's (L,B,3)->(3L,B) scrambling reshape.
__device__ unsigned g_bar_gen;   // monotonic barrier generation
__device__ unsigned g_bar_cnt;   // arrival counter (returns to 0 every barrier)

__constant__ float c_bl[3] = {145.801f, 152.326f, 132.868f};
__constant__ float c_ba[3] = {2.124f, 1.941f, 2.028f};

typedef unsigned long long u64;

// ---------------- f32x2 helpers (verified consistent R8<->R9) ----------------
__device__ __forceinline__ void ffma2(u64 &c, u64 a, u64 b) {
    asm("fma.rn.f32x2 %0, %1, %2, %0;" : "+l"(c) : "l"(a), "l"(b));
}
__device__ __forceinline__ u64 dup2(float x) {
    u64 r; unsigned u = __float_as_uint(x);
    asm("mov.b64 %0, {%1, %1};" : "=l"(r) : "r"(u));
    return r;
}
__device__ __forceinline__ float2 unpk(u64 v) {
    unsigned lo, hi;
    asm("mov.b64 {%0, %1}, %2;" : "=r"(lo), "=r"(hi) : "l"(v));
    float2 f; f.x = __uint_as_float(lo); f.y = __uint_as_float(hi);
    return f;
}

// ---------------- small prep kernels ----------------
__global__ void k_padx(const float* __restrict__ x) {
    int idx = blockIdx.x * 256 + threadIdx.x;
    if (idx >= Mq * KP) return;
    int m = idx / KP, k = idx - m * KP;
    int b = m & 31, t = m >> 5;                       // m = t*32 + b
    g_xpad[idx] = (k < DIN) ? x[((size_t)b * Lq + t) * DIN + k] : 0.0f;   // x is [B][L][Din]
}

__global__ void k_padw(const float* __restrict__ w) {
    int idx = blockIdx.x * 256 + threadIdx.x;
    if (idx >= 2 * Gg * KP) return;
    int r = idx / KP, k = idx - r * KP;
    g_wpad[idx] = (k < DIN) ? w[(size_t)r * DIN + k] : 0.0f;
}

__global__ void k_bias(const float* __restrict__ bih, const float* __restrict__ bhh) {
    int idx = blockIdx.x * 256 + threadIdx.x;
    if (idx < 2 * Gg) g_bias[idx] = bih[idx] + bhh[idx];
}

__global__ void k_zero() {
    int idx = blockIdx.x * 256 + threadIdx.x;
    if (idx < 2 * 2 * Hh * Bq) g_hbuf[idx] = 0.0f;
}

// ---------------- tiled f32x2 GEMM: C[m][n] = sum_k A[m][k]*W[z][n][k] + bias[z][n] --------
// BM=BN=128, BK=16, 256 threads, 8x8 microtile via FFMA2 (cols packed in pairs).
__global__ __launch_bounds__(256, 2) void k_gemm(const float* __restrict__ Wext, int K, int mode) {
    const float* A  = (mode == 0) ? g_xpad : g_h0;
    const float* Wb = (mode == 0) ? g_wpad : Wext;

    __shared__ __align__(16) float As[16][128];
    __shared__ __align__(16) float Ws[16][128];

    int tid = threadIdx.x;
    int m0 = blockIdx.x * 128, n0 = blockIdx.y * 128;
    int z  = blockIdx.z;

    const float* Ab = A  + (size_t)m0 * K;
    const float* Wz = Wb + ((size_t)z * Gg + n0) * K;

    u64 acc2[8][4];
#pragma unroll
    for (int i = 0; i < 8; i++)
#pragma unroll
        for (int j = 0; j < 4; j++) acc2[i][j] = 0ull;

    int tx = tid & 15, ty = tid >> 4;
    int lr = tid >> 2, lc = (tid & 3) * 4;

    for (int kt = 0; kt < K; kt += 16) {
        float4 a0 = *(const float4*)(Ab + (size_t)lr        * K + kt + lc);
        float4 a1 = *(const float4*)(Ab + (size_t)(lr + 64) * K + kt + lc);
        float4 w0 = *(const float4*)(Wz + (size_t)lr        * K + kt + lc);
        float4 w1 = *(const float4*)(Wz + (size_t)(lr + 64) * K + kt + lc);
        __syncthreads();
        As[lc + 0][lr] = a0.x; As[lc + 1][lr] = a0.y; As[lc + 2][lr] = a0.z; As[lc + 3][lr] = a0.w;
        As[lc + 0][lr + 64] = a1.x; As[lc + 1][lr + 64] = a1.y; As[lc + 2][lr + 64] = a1.z; As[lc + 3][lr + 64] = a1.w;
        Ws[lc + 0][lr] = w0.x; Ws[lc + 1][lr] = w0.y; Ws[lc + 2][lr] = w0.z; Ws[lc + 3][lr] = w0.w;
        Ws[lc + 0][lr + 64] = w1.x; Ws[lc + 1][lr + 64] = w1.y; Ws[lc + 2][lr + 64] = w1.z; Ws[lc + 3][lr + 64] = w1.w;
        __syncthreads();
#pragma unroll
        for (int k = 0; k < 16; k++) {
            float4 av0 = *(const float4*)&As[k][ty * 8];
            float4 av1 = *(const float4*)&As[k][ty * 8 + 4];
            ulonglong2 b0 = *(const ulonglong2*)&Ws[k][tx * 8];       // cols (0,1),(2,3)
            ulonglong2 b1 = *(const ulonglong2*)&Ws[k][tx * 8 + 4];   // cols (4,5),(6,7)
            float av[8];
            av[0]=av0.x; av[1]=av0.y; av[2]=av0.z; av[3]=av0.w;
            av[4]=av1.x; av[5]=av1.y; av[6]=av1.z; av[7]=av1.w;
#pragma unroll
            for (int i = 0; i < 8; i++) {
                u64 ad = dup2(av[i]);
                ffma2(acc2[i][0], ad, b0.x);
                ffma2(acc2[i][1], ad, b0.y);
                ffma2(acc2[i][2], ad, b1.x);
                ffma2(acc2[i][3], ad, b1.y);
            }
        }
    }

    float bb[8];
#pragma unroll
    for (int j = 0; j < 8; j++) bb[j] = g_bias[z * Gg + n0 + tx * 8 + j];

    float* Cb = g_ct + ((size_t)z * Mq + m0) * Gg + n0;
#pragma unroll
    for (int i = 0; i < 8; i++) {
        float2 q0 = unpk(acc2[i][0]), q1 = unpk(acc2[i][1]);
        float2 q2 = unpk(acc2[i][2]), q3 = unpk(acc2[i][3]);
        float4 v0, v1;
        v0.x = q0.x + bb[0]; v0.y = q0.y + bb[1]; v0.z = q1.x + bb[2]; v0.w = q1.y + bb[3];
        v1.x = q2.x + bb[4]; v1.y = q2.y + bb[5]; v1.z = q3.x + bb[6]; v1.w = q3.y + bb[7];
        *(float4*)&Cb[(size_t)(ty * 8 + i) * Gg + tx * 8]     = v0;
        *(float4*)&Cb[(size_t)(ty * 8 + i) * Gg + tx * 8 + 4] = v1;
    }
}

// ---------------- transpose g_ct [d][m=t*32+b][n] -> g_xp [d][t][n][b] ----------------
__global__ __launch_bounds__(256) void k_trans() {
    __shared__ float tile[32][33];
    int nc = blockIdx.x * 32, t = blockIdx.y, d = blockIdx.z;
    int tid = threadIdx.x;
    const float* src = g_ct + ((size_t)d * Mq + (size_t)t * Bq) * Gg;
#pragma unroll
    for (int i = 0; i < 4; i++) {
        int idx = tid + i * 256;
        int b = idx >> 5, n = idx & 31;
        tile[b][n] = src[(size_t)b * Gg + nc + n];
    }
    __syncthreads();
    float* dst = g_xp + (((size_t)d * Lq + t) * Gg + nc) * Bq;
#pragma unroll
    for (int i = 0; i < 4; i++) {
        int idx = tid + i * 256;
        int n = idx >> 5, b = idx & 31;
        dst[(size_t)n * Bq + b] = tile[b][n];
    }
}

// ---------------- software grid barrier (all RBLK blocks resident) ----------------
__device__ __forceinline__ void grid_bar() {
    __syncthreads();
    if (threadIdx.x == 0) {
        unsigned gen = *((volatile unsigned*)&g_bar_gen);
        __threadfence();                       // publish this block's h writes
        unsigned my = atomicAdd(&g_bar_cnt, 1u);
        if (my == RBLK - 1) {
            atomicExch(&g_bar_cnt, 0u);        // reset strictly before release
            __threadfence();
            atomicExch(&g_bar_gen, gen + 1u);  // release
        } else {
            while (*((volatile unsigned*)&g_bar_gen) == gen) { __nanosleep(64); }
            __threadfence();                   // acquire side before consuming peers' h
        }
    }
    __syncthreads();
}

// ---------------- persistent bidirectional LSTM recurrence (one launch per layer) -------
// 100 blocks x 256 threads. Blocks 0..49 -> dir0, 50..99 -> dir1.
// 8 warps/block, each warp owns exactly 2 hidden units (lane = batch). 50*8*2 = 800 exact.
// Cell state in registers. h ping-pong layout: [buf][dir][k/4][b][4] -> one float4/lane.
__global__ __launch_bounds__(256) void k_rec(const float* __restrict__ whh, int mode) {
    const int warp = threadIdx.x >> 5, lane = threadIdx.x & 31;
    const int d  = (blockIdx.x >= DBLK) ? 1 : 0;
    const int j0 = (blockIdx.x - d * DBLK) * 16 + warp * 2;  // units j0, j0+1 (both < 800)

    // weight row pointers: gate g (i,f,g,o), unit j -> row (d*4H + g*H + j) of [800]
    const float* Wr[2][4];
#pragma unroll
    for (int i = 0; i < 2; i++)
#pragma unroll
        for (int g4 = 0; g4 < 4; g4++)
            Wr[i][g4] = whh + ((size_t)d * Gg + (size_t)g4 * Hh + (j0 + i)) * Hh;

    float c0 = 0.0f, c1 = 0.0f;
    float* hout = mode ? g_h1 : g_h0;

    for (int t = 0; t < Lq; t++) {
        const int time = d ? (Lq - 1 - t) : t;
        const float* hp = g_hbuf + ((size_t)(t & 1) * 2 + d) * ((size_t)Hh * Bq);
        float*       hn = g_hbuf + ((size_t)((t + 1) & 1) * 2 + d) * ((size_t)Hh * Bq);
        const float* xpb = g_xp + ((size_t)d * Lq + time) * ((size_t)Gg * Bq);

        float acc[2][4];
#pragma unroll
        for (int i = 0; i < 2; i++)
#pragma unroll
            for (int g4 = 0; g4 < 4; g4++)
                acc[i][g4] = xpb[((size_t)g4 * Hh + (j0 + i)) * Bq + lane];

        const float4* hp4 = (const float4*)hp;
#pragma unroll 2
        for (int k = 0; k < Hh; k += 4) {
            float4 h4 = __ldcg(hp4 + ((k >> 2) * Bq + lane));   // L2-coherent (bypass L1)
#pragma unroll
            for (int i = 0; i < 2; i++)
#pragma unroll
                for (int g4 = 0; g4 < 4; g4++) {
                    float4 w4 = *(const float4*)(Wr[i][g4] + k);  // warp-uniform, L1-cached
                    float a = acc[i][g4];
                    a = fmaf(h4.x, w4.x, a);
                    a = fmaf(h4.y, w4.y, a);
                    a = fmaf(h4.z, w4.z, a);
                    a = fmaf(h4.w, w4.w, a);
                    acc[i][g4] = a;
                }
        }

#pragma unroll
        for (int i = 0; i < 2; i++) {
            int j = j0 + i;
            float ai = acc[i][0], af = acc[i][1], ag = acc[i][2], ao = acc[i][3];
            float si = 1.0f / (1.0f + expf(-ai));
            float sf = 1.0f / (1.0f + expf(-af));
            float so = 1.0f / (1.0f + expf(-ao));
            float tg = tanhf(ag);
            float cprev = i ? c1 : c0;
            float cn = sf * cprev + si * tg;
            float hv = so * tanhf(cn);
            if (i) c1 = cn; else c0 = cn;
            hn[((size_t)(j >> 2) * Bq + lane) * 4 + (j & 3)] = hv;
            hout[((size_t)time * Bq + lane) * H2 + (size_t)d * Hh + j] = hv;
        }
        grid_bar();
    }
}

// ---------------- logits = h1 @ w_lin^T + b_lin ----------------
__global__ __launch_bounds__(256) void k_logits(const float* __restrict__ wlin,
                                                const float* __restrict__ blin) {
    __shared__ float sh[H2];
    int t = blockIdx.x, b = blockIdx.y;
    const float* hrow = g_h1 + ((size_t)t * Bq + b) * H2;
    for (int i = threadIdx.x; i < H2; i += 256) sh[i] = hrow[i];
    __syncthreads();
    int warp = threadIdx.x >> 5, lane = threadIdx.x & 31;
    for (int n = warp; n < 20; n += 8) {
        float acc = 0.0f;
        const float* wr = wlin + (size_t)n * H2;
        for (int k = lane; k < H2; k += 32) acc = fmaf(sh[k], wr[k], acc);
#pragma unroll
        for (int off = 16; off; off >>= 1) acc += __shfl_xor_sync(0xffffffffu, acc, off);
        if (lane == 0) g_logits[((size_t)t * Bq + b) * 20 + n] = acc + blin[n];
    }
}

// ---------------- softmax over BATCH axis + alphabet angularization ----------------
// Stores phi in NATURAL [l][b][jj] row-major order into g_ang. The reference's
// ang.reshape(L*3, B) is a raw row-major reinterpretation of this exact buffer.
__global__ void k_angles(const float* __restrict__ alpha) {
    int l = blockIdx.x, lane = threadIdx.x;  // 32 threads, lane = batch
    const float* row = g_logits + ((size_t)l * Bq + lane) * 20;
    float p[20];
#pragma unroll
    for (int n = 0; n < 20; n++) p[n] = row[n];
#pragma unroll
    for (int n = 0; n < 20; n++) {
        float v = p[n], mx = v;
        for (int off = 16; off; off >>= 1) mx = fmaxf(mx, __shfl_xor_sync(0xffffffffu, mx, off));
        float e = expf(v - mx), s = e;
        for (int off = 16; off; off >>= 1) s += __shfl_xor_sync(0xffffffffu, s, off);
        p[n] = e / s;                         // softmax over batch dim (axis=1 of [L,B,20])
    }
#pragma unroll
    for (int jj = 0; jj < 3; jj++) {
        float ss = 0.0f, cc = 0.0f;
        for (int n = 0; n < 20; n++) {
            float al = alpha[n * 3 + jj];
            ss = fmaf(p[n], sinf(al), ss);
            cc = fmaf(p[n], cosf(al), cc);
        }
        g_ang[((size_t)l * Bq + lane) * 3 + jj] = atan2f(ss, cc);
    }
}

// ---------------- NeRF backbone extension: sequential scan, lane = scan column -------
// phis[s][col] = g_ang viewed flat as [2100][32]  (reference's scrambling reshape).
// r, theta indexed by s % 3 (tiled per row, batch-uniform).
__global__ void k_nerf(float* __restrict__ out) {
    int lane = threadIdx.x;
    float ax = 0.f,   ay = 0.f,   az = 0.f;
    float bx = 100.f, by = 0.f,   bz = 0.f;
    float cx = 200.f, cy = 100.f, cz = 0.f;
    float d0c[3], rstc[3];
#pragma unroll
    for (int jj = 0; jj < 3; jj++) {
        d0c[jj]  = -c_bl[jj] * cosf(c_ba[jj]);
        rstc[jj] =  c_bl[jj] * sinf(c_ba[jj]);
    }

    float nphi = g_ang[lane];
    for (int s = 0; s < 2100; s++) {
        float phi = nphi;
        if (s + 1 < 2100) nphi = g_ang[(size_t)(s + 1) * Bq + lane];
        int jj = s - (s / 3) * 3;
        float d0 = d0c[jj];
        float sp, cp;
        sincosf(phi, &sp, &cp);
        float d1 = rstc[jj] * cp;
        float d2 = rstc[jj] * sp;

        float ux = cx - bx, uy = cy - by, uz = cz - bz;
        float inv = 1.0f / (sqrtf(ux * ux + uy * uy + uz * uz) + 1e-12f);
        float bcx = ux * inv, bcy = uy * inv, bcz = uz * inv;

        float vx = bx - ax, vy = by - ay, vz = bz - az;
        float nx = vy * bcz - vz * bcy;
        float ny = vz * bcx - vx * bcz;
        float nz = vx * bcy - vy * bcx;
        float inv2 = 1.0f / (sqrtf(nx * nx + ny * ny + nz * nz) + 1e-12f);
        nx *= inv2; ny *= inv2; nz *= inv2;

        float mx = ny * bcz - nz * bcy;
        float my = nz * bcx - nx * bcz;
        float mz = nx * bcy - ny * bcx;

        float Dx = cx + d0 * bcx + d1 * mx + d2 * nx;
        float Dy = cy + d0 * bcy + d1 * my + d2 * ny;
        float Dz = cz + d0 * bcz + d1 * mz + d2 * nz;

        size_t o = ((size_t)s * Bq + lane) * 3;
        out[o] = Dx; out[o + 1] = Dy; out[o + 2] = Dz;

        ax = bx; ay = by; az = bz;
        bx = cx; by = cy; bz = cz;
        cx = Dx; cy = Dy; cz = Dz;
    }
}

// ---------------- host orchestration ----------------
extern "C" void kernel_launch(void* const* d_in, const int* in_sizes, int n_in,
                              void* d_out, int out_size) {
    const float* x     = (const float*)d_in[0];
    const float* wih0  = (const float*)d_in[1];
    const float* whh0  = (const float*)d_in[2];
    const float* bih0  = (const float*)d_in[3];
    const float* bhh0  = (const float*)d_in[4];
    const float* wih1  = (const float*)d_in[5];
    const float* whh1  = (const float*)d_in[6];
    const float* bih1  = (const float*)d_in[7];
    const float* bhh1  = (const float*)d_in[8];
    const float* wlin  = (const float*)d_in[9];
    const float* blin  = (const float*)d_in[10];
    const float* alpha = (const float*)d_in[11];
    float* out = (float*)d_out;

    // ---- layer 0 ----
    k_padx<<<(Mq * KP + 255) / 256, 256>>>(x);
    k_padw<<<(2 * Gg * KP + 255) / 256, 256>>>(wih0);
    k_bias<<<(2 * Gg + 255) / 256, 256>>>(bih0, bhh0);
    k_gemm<<<dim3(Mq / 128, Gg / 128, 2), 256>>>(nullptr, KP, 0);
    k_trans<<<dim3(Gg / 32, Lq, 2), 256>>>();
    k_zero<<<(2 * 2 * Hh * Bq + 255) / 256, 256>>>();
    k_rec<<<RBLK, 256>>>(whh0, 0);

    // ---- layer 1 ----
    k_bias<<<(2 * Gg + 255) / 256, 256>>>(bih1, bhh1);
    k_gemm<<<dim3(Mq / 128, Gg / 128, 2), 256>>>(wih1, H2, 1);
    k_trans<<<dim3(Gg / 32, Lq, 2), 256>>>();
    k_zero<<<(2 * 2 * Hh * Bq + 255) / 256, 256>>>();
    k_rec<<<RBLK, 256>>>(whh1, 1);

    // ---- head + geometry ----
    k_logits<<<dim3(Lq, Bq), 256>>>(wlin, blin);
    k_angles<<<Lq, 32>>>(alpha);
    k_nerf<<<1, 32>>>(out);
}

// round 13
// speedup vs baseline: 2.4110x; 2.4110x over previous
#include <cuda_runtime.h>
#include <math.h>

// Problem constants
#define Lq   700
#define Bq   32
#define DIN  41
#define Hh   800
#define Gg   3200      // 4*H
#define H2   1600      // 2*H
#define Mq   22400     // L*B
#define KP   48        // padded K for layer-0 input projection

// persistent recurrence: 134 blocks (1/SM via 153.6KB smem), split by direction
#define RBLK2 134
#define DBLK2 67       // blocks per direction; 67*12 = 804 >= 800 unit slots
#define UPB   12       // units per block
#define WPB   6        // warps per block (2 units per warp)
#define SMEMW (UPB*4*Hh)          // floats of weight smem per block (38400)
#define SMEMB (SMEMW*4)           // bytes (153600)

// ---------------- device scratch (static; no runtime allocation) ----------------
__device__ __align__(16) float g_xp  [(size_t)2*Lq*Gg*Bq];  // gate preacts [dir][t][n][b]
__device__ __align__(16) float g_ct  [(size_t)2*Mq*Gg];     // GEMM out [dir][m][n]
__device__ __align__(16) float g_h0  [(size_t)Mq*H2];       // layer-0 hidden [t][b][1600]
__device__ __align__(16) float g_h1  [(size_t)Mq*H2];       // layer-1 hidden
__device__ __align__(16) float g_hbuf[2*2*Hh*Bq];           // ping-pong h [buf][dir][k/4][b][4]
__device__ __align__(16) float g_xpad[(size_t)Mq*KP];       // padded x  [m=t*32+b][48]
__device__ __align__(16) float g_wpad[(size_t)2*Gg*KP];     // padded w_ih_l0
__device__ float g_bias[2*Gg];
__device__ float g_logits[(size_t)Mq*20];
__device__ float g_ang[(size_t)Lq*Bq*3];    // angles in NATURAL [l][b][jj] order; NeRF reads
                                            // this flat as [2100][32] == reference's reshape.
__device__ unsigned g_gen[2];    // per-direction barrier generation (monotonic)
__device__ unsigned g_cnt[2];    // per-direction arrival counters

__constant__ float c_bl[3] = {145.801f, 152.326f, 132.868f};
__constant__ float c_ba[3] = {2.124f, 1.941f, 2.028f};

typedef unsigned long long u64;

// ---------------- f32x2 helpers (numerics cross-validated R8<->R9) ----------------
__device__ __forceinline__ void ffma2(u64 &c, u64 a, u64 b) {
    asm("fma.rn.f32x2 %0, %1, %2, %0;" : "+l"(c) : "l"(a), "l"(b));
}
__device__ __forceinline__ u64 dup2(float x) {
    u64 r; unsigned u = __float_as_uint(x);
    asm("mov.b64 %0, {%1, %1};" : "=l"(r) : "r"(u));
    return r;
}
__device__ __forceinline__ u64 pklo(float lo) {   // (lo, 0)
    u64 r;
    asm("mov.b64 %0, {%1, %2};" : "=l"(r) : "r"(__float_as_uint(lo)), "r"(0u));
    return r;
}
__device__ __forceinline__ float2 unpk(u64 v) {
    unsigned lo, hi;
    asm("mov.b64 {%0, %1}, %2;" : "=r"(lo), "=r"(hi) : "l"(v));
    float2 f; f.x = __uint_as_float(lo); f.y = __uint_as_float(hi);
    return f;
}
// L2-coherent 16B load as two f32x2 lanes (bypass L1: cross-SM h traffic)
__device__ __forceinline__ ulonglong2 ldcg2(const void* p) {
    ulonglong2 v;
    asm volatile("ld.global.cg.v2.u64 {%0, %1}, [%2];" : "=l"(v.x), "=l"(v.y) : "l"(p));
    return v;
}

// ---------------- small prep kernels ----------------
__global__ void k_padx(const float* __restrict__ x) {
    int idx = blockIdx.x * 256 + threadIdx.x;
    if (idx >= Mq * KP) return;
    int m = idx / KP, k = idx - m * KP;
    int b = m & 31, t = m >> 5;                       // m = t*32 + b
    g_xpad[idx] = (k < DIN) ? x[((size_t)b * Lq + t) * DIN + k] : 0.0f;   // x is [B][L][Din]
}

__global__ void k_padw(const float* __restrict__ w) {
    int idx = blockIdx.x * 256 + threadIdx.x;
    if (idx >= 2 * Gg * KP) return;
    int r = idx / KP, k = idx - r * KP;
    g_wpad[idx] = (k < DIN) ? w[(size_t)r * DIN + k] : 0.0f;
}

__global__ void k_bias(const float* __restrict__ bih, const float* __restrict__ bhh) {
    int idx = blockIdx.x * 256 + threadIdx.x;
    if (idx < 2 * Gg) g_bias[idx] = bih[idx] + bhh[idx];
}

__global__ void k_zero() {
    int idx = blockIdx.x * 256 + threadIdx.x;
    if (idx < 2 * 2 * Hh * Bq) g_hbuf[idx] = 0.0f;
}

// ---------------- tiled f32x2 GEMM: C[m][n] = sum_k A[m][k]*W[z][n][k] + bias[z][n] --------
// (unchanged from passing R11 — 1.3 ms total, not the bottleneck this round)
__global__ __launch_bounds__(256, 2) void k_gemm(const float* __restrict__ Wext, int K, int mode) {
    const float* A  = (mode == 0) ? g_xpad : g_h0;
    const float* Wb = (mode == 0) ? g_wpad : Wext;

    __shared__ __align__(16) float As[16][128];
    __shared__ __align__(16) float Ws[16][128];

    int tid = threadIdx.x;
    int m0 = blockIdx.x * 128, n0 = blockIdx.y * 128;
    int z  = blockIdx.z;

    const float* Ab = A  + (size_t)m0 * K;
    const float* Wz = Wb + ((size_t)z * Gg + n0) * K;

    u64 acc2[8][4];
#pragma unroll
    for (int i = 0; i < 8; i++)
#pragma unroll
        for (int j = 0; j < 4; j++) acc2[i][j] = 0ull;

    int tx = tid & 15, ty = tid >> 4;
    int lr = tid >> 2, lc = (tid & 3) * 4;

    for (int kt = 0; kt < K; kt += 16) {
        float4 a0 = *(const float4*)(Ab + (size_t)lr        * K + kt + lc);
        float4 a1 = *(const float4*)(Ab + (size_t)(lr + 64) * K + kt + lc);
        float4 w0 = *(const float4*)(Wz + (size_t)lr        * K + kt + lc);
        float4 w1 = *(const float4*)(Wz + (size_t)(lr + 64) * K + kt + lc);
        __syncthreads();
        As[lc + 0][lr] = a0.x; As[lc + 1][lr] = a0.y; As[lc + 2][lr] = a0.z; As[lc + 3][lr] = a0.w;
        As[lc + 0][lr + 64] = a1.x; As[lc + 1][lr + 64] = a1.y; As[lc + 2][lr + 64] = a1.z; As[lc + 3][lr + 64] = a1.w;
        Ws[lc + 0][lr] = w0.x; Ws[lc + 1][lr] = w0.y; Ws[lc + 2][lr] = w0.z; Ws[lc + 3][lr] = w0.w;
        Ws[lc + 0][lr + 64] = w1.x; Ws[lc + 1][lr + 64] = w1.y; Ws[lc + 2][lr + 64] = w1.z; Ws[lc + 3][lr + 64] = w1.w;
        __syncthreads();
#pragma unroll
        for (int k = 0; k < 16; k++) {
            float4 av0 = *(const float4*)&As[k][ty * 8];
            float4 av1 = *(const float4*)&As[k][ty * 8 + 4];
            ulonglong2 b0 = *(const ulonglong2*)&Ws[k][tx * 8];
            ulonglong2 b1 = *(const ulonglong2*)&Ws[k][tx * 8 + 4];
            float av[8];
            av[0]=av0.x; av[1]=av0.y; av[2]=av0.z; av[3]=av0.w;
            av[4]=av1.x; av[5]=av1.y; av[6]=av1.z; av[7]=av1.w;
#pragma unroll
            for (int i = 0; i < 8; i++) {
                u64 ad = dup2(av[i]);
                ffma2(acc2[i][0], ad, b0.x);
                ffma2(acc2[i][1], ad, b0.y);
                ffma2(acc2[i][2], ad, b1.x);
                ffma2(acc2[i][3], ad, b1.y);
            }
        }
    }

    float bb[8];
#pragma unroll
    for (int j = 0; j < 8; j++) bb[j] = g_bias[z * Gg + n0 + tx * 8 + j];

    float* Cb = g_ct + ((size_t)z * Mq + m0) * Gg + n0;
#pragma unroll
    for (int i = 0; i < 8; i++) {
        float2 q0 = unpk(acc2[i][0]), q1 = unpk(acc2[i][1]);
        float2 q2 = unpk(acc2[i][2]), q3 = unpk(acc2[i][3]);
        float4 v0, v1;
        v0.x = q0.x + bb[0]; v0.y = q0.y + bb[1]; v0.z = q1.x + bb[2]; v0.w = q1.y + bb[3];
        v1.x = q2.x + bb[4]; v1.y = q2.y + bb[5]; v1.z = q3.x + bb[6]; v1.w = q3.y + bb[7];
        *(float4*)&Cb[(size_t)(ty * 8 + i) * Gg + tx * 8]     = v0;
        *(float4*)&Cb[(size_t)(ty * 8 + i) * Gg + tx * 8 + 4] = v1;
    }
}

// ---------------- transpose g_ct [d][m=t*32+b][n] -> g_xp [d][t][n][b] ----------------
__global__ __launch_bounds__(256) void k_trans() {
    __shared__ float tile[32][33];
    int nc = blockIdx.x * 32, t = blockIdx.y, d = blockIdx.z;
    int tid = threadIdx.x;
    const float* src = g_ct + ((size_t)d * Mq + (size_t)t * Bq) * Gg;
#pragma unroll
    for (int i = 0; i < 4; i++) {
        int idx = tid + i * 256;
        int b = idx >> 5, n = idx & 31;
        tile[b][n] = src[(size_t)b * Gg + nc + n];
    }
    __syncthreads();
    float* dst = g_xp + (((size_t)d * Lq + t) * Gg + nc) * Bq;
#pragma unroll
    for (int i = 0; i < 4; i++) {
        int idx = tid + i * 256;
        int n = idx >> 5, b = idx & 31;
        dst[(size_t)n * Bq + b] = tile[b][n];
    }
}

// ---------------- per-direction software grid barrier (DBLK2 arrivals) ----------------
__device__ __forceinline__ void grid_bar_d(int d) {
    __syncthreads();
    if (threadIdx.x == 0) {
        unsigned gen = ((volatile unsigned*)g_gen)[d];
        __threadfence();                           // publish this block's h writes
        unsigned my = atomicAdd(&g_cnt[d], 1u);
        if (my == DBLK2 - 1) {
            atomicExch(&g_cnt[d], 0u);             // reset strictly before release
            __threadfence();
            atomicExch(&g_gen[d], gen + 1u);       // release
        } else {
            while (((volatile unsigned*)g_gen)[d] == gen) { __nanosleep(32); }
            __threadfence();                       // acquire before consuming peers' h
        }
    }
    __syncthreads();
}

// ---------------- persistent bidirectional LSTM recurrence (one launch per layer) -------
// 134 blocks x 192 threads, 153.6KB dynamic smem (weights resident for all 700 steps).
// Blocks 0..66 dir0, 67..133 dir1. 6 warps/block, 2 units/warp (lane = batch).
// Inner product via FFMA2 over k-pairs; h via L2-coherent 16B loads; weights via
// warp-uniform LDS.128 broadcast from smem.
__global__ __launch_bounds__(192) void k_rec(const float* __restrict__ whh, int mode) {
    extern __shared__ __align__(16) float sw[];    // [UPB*4][800] rows: r = lu*4 + gate

    const int warp = threadIdx.x >> 5, lane = threadIdx.x & 31;
    const int d   = (blockIdx.x >= DBLK2) ? 1 : 0;
    const int blk = blockIdx.x - d * DBLK2;
    const int u0  = blk * UPB;

    // ---- preload this block's 48 weight rows (UPB units x 4 gates x 800 floats) ----
    for (int idx = threadIdx.x; idx < UPB * 4 * (Hh / 4); idx += blockDim.x) {
        int r = idx / (Hh / 4), i = idx - r * (Hh / 4);
        int lu = r >> 2, g = r & 3;
        int j = u0 + lu; if (j > Hh - 1) j = Hh - 1;
        ((float4*)(sw + (size_t)r * Hh))[i] =
            ((const float4*)(whh + ((size_t)d * Gg + (size_t)g * Hh + j) * Hh))[i];
    }
    __syncthreads();

    const int j0 = u0 + warp * 2;                  // units j0, j0+1
    const bool act0 = (j0     < Hh);
    const bool act1 = (j0 + 1 < Hh);
    const int ja = act0 ? j0     : Hh - 1;
    const int jb = act1 ? j0 + 1 : Hh - 1;

    // smem row bases for the warp's 8 (unit,gate) rows
    const float* wr[2][4];
#pragma unroll
    for (int i = 0; i < 2; i++)
#pragma unroll
        for (int g = 0; g < 4; g++)
            wr[i][g] = sw + (size_t)((warp * 2 + i) * 4 + g) * Hh;

    float c0 = 0.0f, c1 = 0.0f;
    float* hout = mode ? g_h1 : g_h0;

    for (int t = 0; t < Lq; t++) {
        const int time = d ? (Lq - 1 - t) : t;
        const float* hp = g_hbuf + ((size_t)(t & 1) * 2 + d) * ((size_t)Hh * Bq);
        float*       hn = g_hbuf + ((size_t)((t + 1) & 1) * 2 + d) * ((size_t)Hh * Bq);
        const float* xpb = g_xp + ((size_t)d * Lq + time) * ((size_t)Gg * Bq);

        u64 acc[2][4];
#pragma unroll
        for (int g = 0; g < 4; g++) {
            acc[0][g] = pklo(xpb[((size_t)g * Hh + ja) * Bq + lane]);
            acc[1][g] = pklo(xpb[((size_t)g * Hh + jb) * Bq + lane]);
        }

        const ulonglong2* hp2 = (const ulonglong2*)hp;
        for (int k = 0; k < Hh; k += 8) {
            ulonglong2 hA = ldcg2(hp2 + ((k >> 2)     * Bq + lane));  // h[k..k+3]  (2 pairs)
            ulonglong2 hB = ldcg2(hp2 + (((k >> 2)+1) * Bq + lane));  // h[k+4..k+7]
#pragma unroll
            for (int i = 0; i < 2; i++)
#pragma unroll
                for (int g = 0; g < 4; g++) {
                    ulonglong2 wA = *(const ulonglong2*)(wr[i][g] + k);      // LDS.128 broadcast
                    ulonglong2 wB = *(const ulonglong2*)(wr[i][g] + k + 4);
                    ffma2(acc[i][g], hA.x, wA.x);
                    ffma2(acc[i][g], hA.y, wA.y);
                    ffma2(acc[i][g], hB.x, wB.x);
                    ffma2(acc[i][g], hB.y, wB.y);
                }
        }

#pragma unroll
        for (int i = 0; i < 2; i++) {
            float2 pi = unpk(acc[i][0]), pf = unpk(acc[i][1]);
            float2 pg = unpk(acc[i][2]), po = unpk(acc[i][3]);
            float ai = pi.x + pi.y, af = pf.x + pf.y;
            float ag = pg.x + pg.y, ao = po.x + po.y;
            float si = 1.0f / (1.0f + expf(-ai));
            float sf = 1.0f / (1.0f + expf(-af));
            float so = 1.0f / (1.0f + expf(-ao));
            float tg = tanhf(ag);
            float cprev = i ? c1 : c0;
            float cn = sf * cprev + si * tg;
            float hv = so * tanhf(cn);
            bool act = i ? act1 : act0;
            int  j   = i ? jb : ja;
            if (act) {
                if (i) c1 = cn; else c0 = cn;
                hn[((size_t)(j >> 2) * Bq + lane) * 4 + (j & 3)] = hv;
                hout[((size_t)time * Bq + lane) * H2 + (size_t)d * Hh + j] = hv;
            }
        }
        grid_bar_d(d);
    }
}

// ---------------- logits = h1 @ w_lin^T + b_lin ----------------
__global__ __launch_bounds__(256) void k_logits(const float* __restrict__ wlin,
                                                const float* __restrict__ blin) {
    __shared__ float sh[H2];
    int t = blockIdx.x, b = blockIdx.y;
    const float* hrow = g_h1 + ((size_t)t * Bq + b) * H2;
    for (int i = threadIdx.x; i < H2; i += 256) sh[i] = hrow[i];
    __syncthreads();
    int warp = threadIdx.x >> 5, lane = threadIdx.x & 31;
    for (int n = warp; n < 20; n += 8) {
        float acc = 0.0f;
        const float* wr = wlin + (size_t)n * H2;
        for (int k = lane; k < H2; k += 32) acc = fmaf(sh[k], wr[k], acc);
#pragma unroll
        for (int off = 16; off; off >>= 1) acc += __shfl_xor_sync(0xffffffffu, acc, off);
        if (lane == 0) g_logits[((size_t)t * Bq + b) * 20 + n] = acc + blin[n];
    }
}

// ---------------- softmax over BATCH axis + alphabet angularization ----------------
__global__ void k_angles(const float* __restrict__ alpha) {
    int l = blockIdx.x, lane = threadIdx.x;  // 32 threads, lane = batch
    const float* row = g_logits + ((size_t)l * Bq + lane) * 20;
    float p[20];
#pragma unroll
    for (int n = 0; n < 20; n++) p[n] = row[n];
#pragma unroll
    for (int n = 0; n < 20; n++) {
        float v = p[n], mx = v;
        for (int off = 16; off; off >>= 1) mx = fmaxf(mx, __shfl_xor_sync(0xffffffffu, mx, off));
        float e = expf(v - mx), s = e;
        for (int off = 16; off; off >>= 1) s += __shfl_xor_sync(0xffffffffu, s, off);
        p[n] = e / s;                         // softmax over batch dim (axis=1 of [L,B,20])
    }
#pragma unroll
    for (int jj = 0; jj < 3; jj++) {
        float ss = 0.0f, cc = 0.0f;
        for (int n = 0; n < 20; n++) {
            float al = alpha[n * 3 + jj];
            ss = fmaf(p[n], sinf(al), ss);
            cc = fmaf(p[n], cosf(al), cc);
        }
        g_ang[((size_t)l * Bq + lane) * 3 + jj] = atan2f(ss, cc);
    }
}

// ---------------- NeRF backbone extension: sequential scan, lane = scan column -------
__global__ void k_nerf(float* __restrict__ out) {
    int lane = threadIdx.x;
    float ax = 0.f,   ay = 0.f,   az = 0.f;
    float bx = 100.f, by = 0.f,   bz = 0.f;
    float cx = 200.f, cy = 100.f, cz = 0.f;
    float d0c[3], rstc[3];
#pragma unroll
    for (int jj = 0; jj < 3; jj++) {
        d0c[jj]  = -c_bl[jj] * cosf(c_ba[jj]);
        rstc[jj] =  c_bl[jj] * sinf(c_ba[jj]);
    }

    float nphi = g_ang[lane];
    for (int s = 0; s < 2100; s++) {
        float phi = nphi;
        if (s + 1 < 2100) nphi = g_ang[(size_t)(s + 1) * Bq + lane];
        int jj = s - (s / 3) * 3;
        float d0 = d0c[jj];
        float sp, cp;
        sincosf(phi, &sp, &cp);
        float d1 = rstc[jj] * cp;
        float d2 = rstc[jj] * sp;

        float ux = cx - bx, uy = cy - by, uz = cz - bz;
        float inv = 1.0f / (sqrtf(ux * ux + uy * uy + uz * uz) + 1e-12f);
        float bcx = ux * inv, bcy = uy * inv, bcz = uz * inv;

        float vx = bx - ax, vy = by - ay, vz = bz - az;
        float nx = vy * bcz - vz * bcy;
        float ny = vz * bcx - vx * bcz;
        float nz = vx * bcy - vy * bcx;
        float inv2 = 1.0f / (sqrtf(nx * nx + ny * ny + nz * nz) + 1e-12f);
        nx *= inv2; ny *= inv2; nz *= inv2;

        float mx = ny * bcz - nz * bcy;
        float my = nz * bcx - nx * bcz;
        float mz = nx * bcy - ny * bcx;

        float Dx = cx + d0 * bcx + d1 * mx + d2 * nx;
        float Dy = cy + d0 * bcy + d1 * my + d2 * ny;
        float Dz = cz + d0 * bcz + d1 * mz + d2 * nz;

        size_t o = ((size_t)s * Bq + lane) * 3;
        out[o] = Dx; out[o + 1] = Dy; out[o + 2] = Dz;

        ax = bx; ay = by; az = bz;
        bx = cx; by = cy; bz = cz;
        cx = Dx; cy = Dy; cz = Dz;
    }
}

// ---------------- host orchestration ----------------
extern "C" void kernel_launch(void* const* d_in, const int* in_sizes, int n_in,
                              void* d_out, int out_size) {
    const float* x     = (const float*)d_in[0];
    const float* wih0  = (const float*)d_in[1];
    const float* whh0  = (const float*)d_in[2];
    const float* bih0  = (const float*)d_in[3];
    const float* bhh0  = (const float*)d_in[4];
    const float* wih1  = (const float*)d_in[5];
    const float* whh1  = (const float*)d_in[6];
    const float* bih1  = (const float*)d_in[7];
    const float* bhh1  = (const float*)d_in[8];
    const float* wlin  = (const float*)d_in[9];
    const float* blin  = (const float*)d_in[10];
    const float* alpha = (const float*)d_in[11];
    float* out = (float*)d_out;

    // allow 153.6KB dynamic smem for the persistent recurrence kernel (idempotent)
    cudaFuncSetAttribute(k_rec, cudaFuncAttributeMaxDynamicSharedMemorySize, SMEMB);

    // ---- layer 0 ----
    k_padx<<<(Mq * KP + 255) / 256, 256>>>(x);
    k_padw<<<(2 * Gg * KP + 255) / 256, 256>>>(wih0);
    k_bias<<<(2 * Gg + 255) / 256, 256>>>(bih0, bhh0);
    k_gemm<<<dim3(Mq / 128, Gg / 128, 2), 256>>>(nullptr, KP, 0);
    k_trans<<<dim3(Gg / 32, Lq, 2), 256>>>();
    k_zero<<<(2 * 2 * Hh * Bq + 255) / 256, 256>>>();
    k_rec<<<RBLK2, 192, SMEMB>>>(whh0, 0);

    // ---- layer 1 ----
    k_bias<<<(2 * Gg + 255) / 256, 256>>>(bih1, bhh1);
    k_gemm<<<dim3(Mq / 128, Gg / 128, 2), 256>>>(wih1, H2, 1);
    k_trans<<<dim3(Gg / 32, Lq, 2), 256>>>();
    k_zero<<<(2 * 2 * Hh * Bq + 255) / 256, 256>>>();
    k_rec<<<RBLK2, 192, SMEMB>>>(whh1, 1);

    // ---- head + geometry ----
    k_logits<<<dim3(Lq, Bq), 256>>>(wlin, blin);
    k_angles<<<Lq, 32>>>(alpha);
    k_nerf<<<1, 32>>>(out);
}

// round 14
// speedup vs baseline: 4.2775x; 1.7742x over previous
#include <cuda_runtime.h>
#include <math.h>

// Problem constants
#define Lq   700
#define Bq   32
#define DIN  41
#define Hh   800
#define Gg   3200      // 4*H
#define H2   1600      // 2*H
#define Mq   22400     // L*B
#define KP   48        // padded K for layer-0 input projection

// persistent recurrence: 134 blocks (1/SM via 204.8KB smem), split by direction
#define RBLK2 134
#define DBLK2 67       // blocks per direction; 67*12 = 804 >= 800 unit slots
#define UPB   12       // units per block
#define SMEMW (UPB*4*Hh)            // weight floats per block (38400 = 153.6KB)
#define HCH   200                   // h chunk size (k values per chunk)
#define HCHF4 (HCH*Bq/4)            // float4s per chunk (1600 = 25.6KB)
#define SMEMB ((SMEMW + 2*HCH*Bq)*4)  // 204800 bytes

// ---------------- device scratch (static; no runtime allocation) ----------------
__device__ __align__(16) float g_xp  [(size_t)2*Lq*Gg*Bq];  // gate preacts [dir][t][n][b]
__device__ __align__(16) float g_ct  [(size_t)2*Mq*Gg];     // GEMM out [dir][m][n]
__device__ __align__(16) float g_h0  [(size_t)Mq*H2];       // layer-0 hidden [t][b][1600]
__device__ __align__(16) float g_h1  [(size_t)Mq*H2];       // layer-1 hidden
__device__ __align__(16) float g_hbuf[2*2*Hh*Bq];           // ping-pong h [buf][dir][k/4][b][4]
__device__ __align__(16) float g_xpad[(size_t)Mq*KP];       // padded x  [m=t*32+b][48]
__device__ __align__(16) float g_wpad[(size_t)2*Gg*KP];     // padded w_ih_l0
__device__ float g_bias[2*Gg];
__device__ float g_logits[(size_t)Mq*20];
__device__ float g_ang[(size_t)Lq*Bq*3];    // angles in NATURAL [l][b][jj] order; NeRF reads
                                            // this flat as [2100][32] == reference's reshape.
__device__ unsigned g_gen[2];    // per-direction barrier generation (monotonic)
__device__ unsigned g_cnt[2];    // per-direction arrival counters

__constant__ float c_bl[3] = {145.801f, 152.326f, 132.868f};
__constant__ float c_ba[3] = {2.124f, 1.941f, 2.028f};

typedef unsigned long long u64;

// ---------------- f32x2 helpers (numerics cross-validated R8<->R9) ----------------
__device__ __forceinline__ void ffma2(u64 &c, u64 a, u64 b) {
    asm("fma.rn.f32x2 %0, %1, %2, %0;" : "+l"(c) : "l"(a), "l"(b));
}
__device__ __forceinline__ u64 dup2(float x) {
    u64 r; unsigned u = __float_as_uint(x);
    asm("mov.b64 %0, {%1, %1};" : "=l"(r) : "r"(u));
    return r;
}
__device__ __forceinline__ u64 pklo(float lo) {   // (lo, 0)
    u64 r;
    asm("mov.b64 %0, {%1, %2};" : "=l"(r) : "r"(__float_as_uint(lo)), "r"(0u));
    return r;
}
__device__ __forceinline__ float2 unpk(u64 v) {
    unsigned lo, hi;
    asm("mov.b64 {%0, %1}, %2;" : "=r"(lo), "=r"(hi) : "l"(v));
    float2 f; f.x = __uint_as_float(lo); f.y = __uint_as_float(hi);
    return f;
}

// cp.async: 16B global->shared, L2-only (.cg) — correct coherence for cross-SM h
#define CP_ASYNC16(dst_u32, src_ptr) \
    asm volatile("cp.async.cg.shared.global [%0], [%1], 16;" :: "r"(dst_u32), "l"(src_ptr))
#define CP_COMMIT() asm volatile("cp.async.commit_group;")
#define CP_WAIT(n)  asm volatile("cp.async.wait_group %0;" :: "n"(n))

// ---------------- small prep kernels ----------------
__global__ void k_padx(const float* __restrict__ x) {
    int idx = blockIdx.x * 256 + threadIdx.x;
    if (idx >= Mq * KP) return;
    int m = idx / KP, k = idx - m * KP;
    int b = m & 31, t = m >> 5;                       // m = t*32 + b
    g_xpad[idx] = (k < DIN) ? x[((size_t)b * Lq + t) * DIN + k] : 0.0f;   // x is [B][L][Din]
}

__global__ void k_padw(const float* __restrict__ w) {
    int idx = blockIdx.x * 256 + threadIdx.x;
    if (idx >= 2 * Gg * KP) return;
    int r = idx / KP, k = idx - r * KP;
    g_wpad[idx] = (k < DIN) ? w[(size_t)r * DIN + k] : 0.0f;
}

__global__ void k_bias(const float* __restrict__ bih, const float* __restrict__ bhh) {
    int idx = blockIdx.x * 256 + threadIdx.x;
    if (idx < 2 * Gg) g_bias[idx] = bih[idx] + bhh[idx];
}

__global__ void k_zero() {
    int idx = blockIdx.x * 256 + threadIdx.x;
    if (idx < 2 * 2 * Hh * Bq) g_hbuf[idx] = 0.0f;
}

// ---------------- tiled f32x2 GEMM: C[m][n] = sum_k A[m][k]*W[z][n][k] + bias[z][n] --------
__global__ __launch_bounds__(256, 2) void k_gemm(const float* __restrict__ Wext, int K, int mode) {
    const float* A  = (mode == 0) ? g_xpad : g_h0;
    const float* Wb = (mode == 0) ? g_wpad : Wext;

    __shared__ __align__(16) float As[16][128];
    __shared__ __align__(16) float Ws[16][128];

    int tid = threadIdx.x;
    int m0 = blockIdx.x * 128, n0 = blockIdx.y * 128;
    int z  = blockIdx.z;

    const float* Ab = A  + (size_t)m0 * K;
    const float* Wz = Wb + ((size_t)z * Gg + n0) * K;

    u64 acc2[8][4];
#pragma unroll
    for (int i = 0; i < 8; i++)
#pragma unroll
        for (int j = 0; j < 4; j++) acc2[i][j] = 0ull;

    int tx = tid & 15, ty = tid >> 4;
    int lr = tid >> 2, lc = (tid & 3) * 4;

    for (int kt = 0; kt < K; kt += 16) {
        float4 a0 = *(const float4*)(Ab + (size_t)lr        * K + kt + lc);
        float4 a1 = *(const float4*)(Ab + (size_t)(lr + 64) * K + kt + lc);
        float4 w0 = *(const float4*)(Wz + (size_t)lr        * K + kt + lc);
        float4 w1 = *(const float4*)(Wz + (size_t)(lr + 64) * K + kt + lc);
        __syncthreads();
        As[lc + 0][lr] = a0.x; As[lc + 1][lr] = a0.y; As[lc + 2][lr] = a0.z; As[lc + 3][lr] = a0.w;
        As[lc + 0][lr + 64] = a1.x; As[lc + 1][lr + 64] = a1.y; As[lc + 2][lr + 64] = a1.z; As[lc + 3][lr + 64] = a1.w;
        Ws[lc + 0][lr] = w0.x; Ws[lc + 1][lr] = w0.y; Ws[lc + 2][lr] = w0.z; Ws[lc + 3][lr] = w0.w;
        Ws[lc + 0][lr + 64] = w1.x; Ws[lc + 1][lr + 64] = w1.y; Ws[lc + 2][lr + 64] = w1.z; Ws[lc + 3][lr + 64] = w1.w;
        __syncthreads();
#pragma unroll
        for (int k = 0; k < 16; k++) {
            float4 av0 = *(const float4*)&As[k][ty * 8];
            float4 av1 = *(const float4*)&As[k][ty * 8 + 4];
            ulonglong2 b0 = *(const ulonglong2*)&Ws[k][tx * 8];
            ulonglong2 b1 = *(const ulonglong2*)&Ws[k][tx * 8 + 4];
            float av[8];
            av[0]=av0.x; av[1]=av0.y; av[2]=av0.z; av[3]=av0.w;
            av[4]=av1.x; av[5]=av1.y; av[6]=av1.z; av[7]=av1.w;
#pragma unroll
            for (int i = 0; i < 8; i++) {
                u64 ad = dup2(av[i]);
                ffma2(acc2[i][0], ad, b0.x);
                ffma2(acc2[i][1], ad, b0.y);
                ffma2(acc2[i][2], ad, b1.x);
                ffma2(acc2[i][3], ad, b1.y);
            }
        }
    }

    float bb[8];
#pragma unroll
    for (int j = 0; j < 8; j++) bb[j] = g_bias[z * Gg + n0 + tx * 8 + j];

    float* Cb = g_ct + ((size_t)z * Mq + m0) * Gg + n0;
#pragma unroll
    for (int i = 0; i < 8; i++) {
        float2 q0 = unpk(acc2[i][0]), q1 = unpk(acc2[i][1]);
        float2 q2 = unpk(acc2[i][2]), q3 = unpk(acc2[i][3]);
        float4 v0, v1;
        v0.x = q0.x + bb[0]; v0.y = q0.y + bb[1]; v0.z = q1.x + bb[2]; v0.w = q1.y + bb[3];
        v1.x = q2.x + bb[4]; v1.y = q2.y + bb[5]; v1.z = q3.x + bb[6]; v1.w = q3.y + bb[7];
        *(float4*)&Cb[(size_t)(ty * 8 + i) * Gg + tx * 8]     = v0;
        *(float4*)&Cb[(size_t)(ty * 8 + i) * Gg + tx * 8 + 4] = v1;
    }
}

// ---------------- transpose g_ct [d][m=t*32+b][n] -> g_xp [d][t][n][b] ----------------
__global__ __launch_bounds__(256) void k_trans() {
    __shared__ float tile[32][33];
    int nc = blockIdx.x * 32, t = blockIdx.y, d = blockIdx.z;
    int tid = threadIdx.x;
    const float* src = g_ct + ((size_t)d * Mq + (size_t)t * Bq) * Gg;
#pragma unroll
    for (int i = 0; i < 4; i++) {
        int idx = tid + i * 256;
        int b = idx >> 5, n = idx & 31;
        tile[b][n] = src[(size_t)b * Gg + nc + n];
    }
    __syncthreads();
    float* dst = g_xp + (((size_t)d * Lq + t) * Gg + nc) * Bq;
#pragma unroll
    for (int i = 0; i < 4; i++) {
        int idx = tid + i * 256;
        int n = idx >> 5, b = idx & 31;
        dst[(size_t)n * Bq + b] = tile[b][n];
    }
}

// ---------------- per-direction software grid barrier (DBLK2 arrivals) ----------------
__device__ __forceinline__ void grid_bar_d(int d) {
    __syncthreads();
    if (threadIdx.x == 0) {
        unsigned gen = ((volatile unsigned*)g_gen)[d];
        __threadfence();                           // publish this block's h writes
        unsigned my = atomicAdd(&g_cnt[d], 1u);
        if (my == DBLK2 - 1) {
            atomicExch(&g_cnt[d], 0u);             // reset strictly before release
            __threadfence();
            atomicExch(&g_gen[d], gen + 1u);       // release
        } else {
            while (((volatile unsigned*)g_gen)[d] == gen) { __nanosleep(32); }
            __threadfence();                       // acquire before consuming peers' h
        }
    }
    __syncthreads();
}

// ---------------- persistent bidirectional LSTM recurrence (one launch per layer) -------
// 134 blocks x 192 threads, 204.8KB dynamic smem:
//   [0 .. 38400)           weights (resident all 700 steps)
//   [38400 .. 38400+6400)  h chunk buffer A (200 k x 32 b)
//   [+6400 .. +12800)      h chunk buffer B
// Per step: 4 chunks of 200 k, cp.async.cg double-buffered (L2-coherent), overlapped
// with FFMA2 compute from smem. 6 warps/block, 2 units/warp, lane = batch.
__global__ __launch_bounds__(192) void k_rec(const float* __restrict__ whh, int mode) {
    extern __shared__ __align__(16) float sw[];
    float* shbuf[2] = { sw + SMEMW, sw + SMEMW + HCH * Bq };

    const int warp = threadIdx.x >> 5, lane = threadIdx.x & 31;
    const int d   = (blockIdx.x >= DBLK2) ? 1 : 0;
    const int blk = blockIdx.x - d * DBLK2;
    const int u0  = blk * UPB;

    // ---- preload this block's 48 weight rows (UPB units x 4 gates x 800 floats) ----
    for (int idx = threadIdx.x; idx < UPB * 4 * (Hh / 4); idx += blockDim.x) {
        int r = idx / (Hh / 4), i = idx - r * (Hh / 4);
        int lu = r >> 2, g = r & 3;
        int j = u0 + lu; if (j > Hh - 1) j = Hh - 1;
        ((float4*)(sw + (size_t)r * Hh))[i] =
            ((const float4*)(whh + ((size_t)d * Gg + (size_t)g * Hh + j) * Hh))[i];
    }
    __syncthreads();

    const int j0 = u0 + warp * 2;                  // units j0, j0+1
    const bool act0 = (j0     < Hh);
    const bool act1 = (j0 + 1 < Hh);
    const int ja = act0 ? j0     : Hh - 1;
    const int jb = act1 ? j0 + 1 : Hh - 1;

    const float* wr[2][4];
#pragma unroll
    for (int i = 0; i < 2; i++)
#pragma unroll
        for (int g = 0; g < 4; g++)
            wr[i][g] = sw + (size_t)((warp * 2 + i) * 4 + g) * Hh;

    unsigned sh_u32[2];
    sh_u32[0] = (unsigned)__cvta_generic_to_shared(shbuf[0]);
    sh_u32[1] = (unsigned)__cvta_generic_to_shared(shbuf[1]);

    float c0 = 0.0f, c1 = 0.0f;
    float* hout = mode ? g_h1 : g_h0;

    for (int t = 0; t < Lq; t++) {
        const int time = d ? (Lq - 1 - t) : t;
        const float4* hp4 = (const float4*)(g_hbuf +
                            ((size_t)(t & 1) * 2 + d) * ((size_t)Hh * Bq));
        float* hn = g_hbuf + ((size_t)((t + 1) & 1) * 2 + d) * ((size_t)Hh * Bq);
        const float* xpb = g_xp + ((size_t)d * Lq + time) * ((size_t)Gg * Bq);

        u64 acc[2][4];
#pragma unroll
        for (int g = 0; g < 4; g++) {
            acc[0][g] = pklo(__ldcs(&xpb[((size_t)g * Hh + ja) * Bq + lane]));
            acc[1][g] = pklo(__ldcs(&xpb[((size_t)g * Hh + jb) * Bq + lane]));
        }

        // ---- prefetch chunks 0 and 1 ----
#pragma unroll
        for (int pc = 0; pc < 2; pc++) {
            const float4* src = hp4 + pc * HCHF4;
            for (int idx = threadIdx.x; idx < HCHF4; idx += 192)
                CP_ASYNC16(sh_u32[pc] + idx * 16, src + idx);
            CP_COMMIT();
        }

        // ---- 4 chunks: compute c while c+1 in flight; prefetch c+2 after use ----
#pragma unroll
        for (int ch = 0; ch < 4; ch++) {
            if (ch < 3) { CP_WAIT(1); } else { CP_WAIT(0); }
            __syncthreads();                       // chunk ch resident for all threads

            const float* buf = shbuf[ch & 1];
            const int kofs = ch * HCH;
            const ulonglong2* b2 = (const ulonglong2*)buf;
#pragma unroll 2
            for (int kk = 0; kk < HCH; kk += 8) {
                ulonglong2 hA = b2[(kk >> 2)       * Bq + lane];   // h[k..k+3]
                ulonglong2 hB = b2[((kk >> 2) + 1) * Bq + lane];   // h[k+4..k+7]
#pragma unroll
                for (int i = 0; i < 2; i++)
#pragma unroll
                    for (int g = 0; g < 4; g++) {
                        const float* w = wr[i][g] + kofs + kk;
                        ulonglong2 wA = *(const ulonglong2*)(w);      // uniform LDS.128
                        ulonglong2 wB = *(const ulonglong2*)(w + 4);
                        ffma2(acc[i][g], hA.x, wA.x);
                        ffma2(acc[i][g], hA.y, wA.y);
                        ffma2(acc[i][g], hB.x, wB.x);
                        ffma2(acc[i][g], hB.y, wB.y);
                    }
            }

            if (ch < 2) {
                __syncthreads();                   // all done reading buf before overwrite
                const float4* src = hp4 + (ch + 2) * HCHF4;
                for (int idx = threadIdx.x; idx < HCHF4; idx += 192)
                    CP_ASYNC16(sh_u32[ch & 1] + idx * 16, src + idx);
                CP_COMMIT();
            }
        }

#pragma unroll
        for (int i = 0; i < 2; i++) {
            float2 pi = unpk(acc[i][0]), pf = unpk(acc[i][1]);
            float2 pg = unpk(acc[i][2]), po = unpk(acc[i][3]);
            float ai = pi.x + pi.y, af = pf.x + pf.y;
            float ag = pg.x + pg.y, ao = po.x + po.y;
            float si = 1.0f / (1.0f + expf(-ai));
            float sf = 1.0f / (1.0f + expf(-af));
            float so = 1.0f / (1.0f + expf(-ao));
            float tg = tanhf(ag);
            float cprev = i ? c1 : c0;
            float cn = sf * cprev + si * tg;
            float hv = so * tanhf(cn);
            bool act = i ? act1 : act0;
            int  j   = i ? jb : ja;
            if (act) {
                if (i) c1 = cn; else c0 = cn;
                hn[((size_t)(j >> 2) * Bq + lane) * 4 + (j & 3)] = hv;
                hout[((size_t)time * Bq + lane) * H2 + (size_t)d * Hh + j] = hv;
            }
        }
        grid_bar_d(d);
    }
}

// ---------------- logits = h1 @ w_lin^T + b_lin ----------------
__global__ __launch_bounds__(256) void k_logits(const float* __restrict__ wlin,
                                                const float* __restrict__ blin) {
    __shared__ float sh[H2];
    int t = blockIdx.x, b = blockIdx.y;
    const float* hrow = g_h1 + ((size_t)t * Bq + b) * H2;
    for (int i = threadIdx.x; i < H2; i += 256) sh[i] = hrow[i];
    __syncthreads();
    int warp = threadIdx.x >> 5, lane = threadIdx.x & 31;
    for (int n = warp; n < 20; n += 8) {
        float acc = 0.0f;
        const float* wr = wlin + (size_t)n * H2;
        for (int k = lane; k < H2; k += 32) acc = fmaf(sh[k], wr[k], acc);
#pragma unroll
        for (int off = 16; off; off >>= 1) acc += __shfl_xor_sync(0xffffffffu, acc, off);
        if (lane == 0) g_logits[((size_t)t * Bq + b) * 20 + n] = acc + blin[n];
    }
}

// ---------------- softmax over BATCH axis + alphabet angularization ----------------
__global__ void k_angles(const float* __restrict__ alpha) {
    int l = blockIdx.x, lane = threadIdx.x;  // 32 threads, lane = batch
    const float* row = g_logits + ((size_t)l * Bq + lane) * 20;
    float p[20];
#pragma unroll
    for (int n = 0; n < 20; n++) p[n] = row[n];
#pragma unroll
    for (int n = 0; n < 20; n++) {
        float v = p[n], mx = v;
        for (int off = 16; off; off >>= 1) mx = fmaxf(mx, __shfl_xor_sync(0xffffffffu, mx, off));
        float e = expf(v - mx), s = e;
        for (int off = 16; off; off >>= 1) s += __shfl_xor_sync(0xffffffffu, s, off);
        p[n] = e / s;                         // softmax over batch dim (axis=1 of [L,B,20])
    }
#pragma unroll
    for (int jj = 0; jj < 3; jj++) {
        float ss = 0.0f, cc = 0.0f;
        for (int n = 0; n < 20; n++) {
            float al = alpha[n * 3 + jj];
            ss = fmaf(p[n], sinf(al), ss);
            cc = fmaf(p[n], cosf(al), cc);
        }
        g_ang[((size_t)l * Bq + lane) * 3 + jj] = atan2f(ss, cc);
    }
}

// ---------------- NeRF backbone extension: sequential scan, lane = scan column -------
__global__ void k_nerf(float* __restrict__ out) {
    int lane = threadIdx.x;
    float ax = 0.f,   ay = 0.f,   az = 0.f;
    float bx = 100.f, by = 0.f,   bz = 0.f;
    float cx = 200.f, cy = 100.f, cz = 0.f;
    float d0c[3], rstc[3];
#pragma unroll
    for (int jj = 0; jj < 3; jj++) {
        d0c[jj]  = -c_bl[jj] * cosf(c_ba[jj]);
        rstc[jj] =  c_bl[jj] * sinf(c_ba[jj]);
    }

    float nphi = g_ang[lane];
    for (int s = 0; s < 2100; s++) {
        float phi = nphi;
        if (s + 1 < 2100) nphi = g_ang[(size_t)(s + 1) * Bq + lane];
        int jj = s - (s / 3) * 3;
        float d0 = d0c[jj];
        float sp, cp;
        sincosf(phi, &sp, &cp);
        float d1 = rstc[jj] * cp;
        float d2 = rstc[jj] * sp;

        float ux = cx - bx, uy = cy - by, uz = cz - bz;
        float inv = 1.0f / (sqrtf(ux * ux + uy * uy + uz * uz) + 1e-12f);
        float bcx = ux * inv, bcy = uy * inv, bcz = uz * inv;

        float vx = bx - ax, vy = by - ay, vz = bz - az;
        float nx = vy * bcz - vz * bcy;
        float ny = vz * bcx - vx * bcz;
        float nz = vx * bcy - vy * bcx;
        float inv2 = 1.0f / (sqrtf(nx * nx + ny * ny + nz * nz) + 1e-12f);
        nx *= inv2; ny *= inv2; nz *= inv2;

        float mx = ny * bcz - nz * bcy;
        float my = nz * bcx - nx * bcz;
        float mz = nx * bcy - ny * bcx;

        float Dx = cx + d0 * bcx + d1 * mx + d2 * nx;
        float Dy = cy + d0 * bcy + d1 * my + d2 * ny;
        float Dz = cz + d0 * bcz + d1 * mz + d2 * nz;

        size_t o = ((size_t)s * Bq + lane) * 3;
        out[o] = Dx; out[o + 1] = Dy; out[o + 2] = Dz;

        ax = bx; ay = by; az = bz;
        bx = cx; by = cy; bz = cz;
        cx = Dx; cy = Dy; cz = Dz;
    }
}

// ---------------- host orchestration ----------------
extern "C" void kernel_launch(void* const* d_in, const int* in_sizes, int n_in,
                              void* d_out, int out_size) {
    const float* x     = (const float*)d_in[0];
    const float* wih0  = (const float*)d_in[1];
    const float* whh0  = (const float*)d_in[2];
    const float* bih0  = (const float*)d_in[3];
    const float* bhh0  = (const float*)d_in[4];
    const float* wih1  = (const float*)d_in[5];
    const float* whh1  = (const float*)d_in[6];
    const float* bih1  = (const float*)d_in[7];
    const float* bhh1  = (const float*)d_in[8];
    const float* wlin  = (const float*)d_in[9];
    const float* blin  = (const float*)d_in[10];
    const float* alpha = (const float*)d_in[11];
    float* out = (float*)d_out;

    // allow 204.8KB dynamic smem for the persistent recurrence kernel (idempotent)
    cudaFuncSetAttribute(k_rec, cudaFuncAttributeMaxDynamicSharedMemorySize, SMEMB);

    // ---- layer 0 ----
    k_padx<<<(Mq * KP + 255) / 256, 256>>>(x);
    k_padw<<<(2 * Gg * KP + 255) / 256, 256>>>(wih0);
    k_bias<<<(2 * Gg + 255) / 256, 256>>>(bih0, bhh0);
    k_gemm<<<dim3(Mq / 128, Gg / 128, 2), 256>>>(nullptr, KP, 0);
    k_trans<<<dim3(Gg / 32, Lq, 2), 256>>>();
    k_zero<<<(2 * 2 * Hh * Bq + 255) / 256, 256>>>();
    k_rec<<<RBLK2, 192, SMEMB>>>(whh0, 0);

    // ---- layer 1 ----
    k_bias<<<(2 * Gg + 255) / 256, 256>>>(bih1, bhh1);
    k_gemm<<<dim3(Mq / 128, Gg / 128, 2), 256>>>(wih1, H2, 1);
    k_trans<<<dim3(Gg / 32, Lq, 2), 256>>>();
    k_zero<<<(2 * 2 * Hh * Bq + 255) / 256, 256>>>();
    k_rec<<<RBLK2, 192, SMEMB>>>(whh1, 1);

    // ---- head + geometry ----
    k_logits<<<dim3(Lq, Bq), 256>>>(wlin, blin);
    k_angles<<<Lq, 32>>>(alpha);
    k_nerf<<<1, 32>>>(out);
}

// round 15
// speedup vs baseline: 4.4393x; 1.0378x over previous
#include <cuda_runtime.h>
#include <math.h>

// Problem constants
#define Lq   700
#define Bq   32
#define DIN  41
#define Hh   800
#define Gg   3200      // 4*H
#define H2   1600      // 2*H
#define Mq   22400     // L*B
#define KP   48        // padded K for layer-0 input projection

// persistent recurrence: 134 blocks (1/SM), split by direction
#define RBLK2 134
#define DBLK2 67       // blocks per direction; 67*12 = 804 >= 800 unit slots
#define UPB   12       // units per block
#define NTH   384      // 12 warps: 6 unit-pairs x 2 k-halves
#define SMEMW (UPB*4*Hh)            // weight floats per block (38400 = 153.6KB)
#define HCH   200                   // h chunk size (k values per chunk)
#define HCHF4 (HCH*Bq/4)            // float4s per chunk (1600 = 25.6KB)
#define REDF  (6*2*4*32*2)          // reduction floats: 6 pairs x 2 units x 4 gates x 32 lanes x f32x2
#define SMEMB ((SMEMW + 2*HCH*Bq + REDF)*4)   // 217088 bytes

// ---------------- device scratch (static; no runtime allocation) ----------------
__device__ __align__(16) float g_xp  [(size_t)2*Lq*Gg*Bq];  // gate preacts [dir][t][n][b]
__device__ __align__(16) float g_ct  [(size_t)2*Mq*Gg];     // GEMM out [dir][m][n]
__device__ __align__(16) float g_h0  [(size_t)Mq*H2];       // layer-0 hidden [t][b][1600]
__device__ __align__(16) float g_h1  [(size_t)Mq*H2];       // layer-1 hidden
__device__ __align__(16) float g_hbuf[2*2*Hh*Bq];           // ping-pong h [buf][dir][k/4][b][4]
__device__ __align__(16) float g_xpad[(size_t)Mq*KP];       // padded x  [m=t*32+b][48]
__device__ __align__(16) float g_wpad[(size_t)2*Gg*KP];     // padded w_ih_l0
__device__ float g_bias[2*Gg];
__device__ float g_logits[(size_t)Mq*20];
__device__ float g_ang[(size_t)Lq*Bq*3];    // angles in NATURAL [l][b][jj] order; NeRF reads
                                            // this flat as [2100][32] == reference's reshape.
__device__ unsigned g_gen[2];    // per-direction barrier generation (monotonic)
__device__ unsigned g_cnt[2];    // per-direction arrival counters

__constant__ float c_bl[3] = {145.801f, 152.326f, 132.868f};
__constant__ float c_ba[3] = {2.124f, 1.941f, 2.028f};

typedef unsigned long long u64;

// ---------------- f32x2 helpers (numerics cross-validated R8<->R9) ----------------
__device__ __forceinline__ void ffma2(u64 &c, u64 a, u64 b) {
    asm("fma.rn.f32x2 %0, %1, %2, %0;" : "+l"(c) : "l"(a), "l"(b));
}
__device__ __forceinline__ u64 dup2(float x) {
    u64 r; unsigned u = __float_as_uint(x);
    asm("mov.b64 %0, {%1, %1};" : "=l"(r) : "r"(u));
    return r;
}
__device__ __forceinline__ u64 pklo(float lo) {   // (lo, 0)
    u64 r;
    asm("mov.b64 %0, {%1, %2};" : "=l"(r) : "r"(__float_as_uint(lo)), "r"(0u));
    return r;
}
__device__ __forceinline__ float2 unpk(u64 v) {
    unsigned lo, hi;
    asm("mov.b64 {%0, %1}, %2;" : "=r"(lo), "=r"(hi) : "l"(v));
    float2 f; f.x = __uint_as_float(lo); f.y = __uint_as_float(hi);
    return f;
}

// cp.async: 16B global->shared, L2-only (.cg) — correct coherence for cross-SM h
#define CP_ASYNC16(dst_u32, src_ptr) \
    asm volatile("cp.async.cg.shared.global [%0], [%1], 16;" :: "r"(dst_u32), "l"(src_ptr))
#define CP_COMMIT() asm volatile("cp.async.commit_group;")
#define CP_WAIT(n)  asm volatile("cp.async.wait_group %0;" :: "n"(n))

// ---------------- small prep kernels ----------------
__global__ void k_padx(const float* __restrict__ x) {
    int idx = blockIdx.x * 256 + threadIdx.x;
    if (idx >= Mq * KP) return;
    int m = idx / KP, k = idx - m * KP;
    int b = m & 31, t = m >> 5;                       // m = t*32 + b
    g_xpad[idx] = (k < DIN) ? x[((size_t)b * Lq + t) * DIN + k] : 0.0f;   // x is [B][L][Din]
}

__global__ void k_padw(const float* __restrict__ w) {
    int idx = blockIdx.x * 256 + threadIdx.x;
    if (idx >= 2 * Gg * KP) return;
    int r = idx / KP, k = idx - r * KP;
    g_wpad[idx] = (k < DIN) ? w[(size_t)r * DIN + k] : 0.0f;
}

__global__ void k_bias(const float* __restrict__ bih, const float* __restrict__ bhh) {
    int idx = blockIdx.x * 256 + threadIdx.x;
    if (idx < 2 * Gg) g_bias[idx] = bih[idx] + bhh[idx];
}

__global__ void k_zero() {
    int idx = blockIdx.x * 256 + threadIdx.x;
    if (idx < 2 * 2 * Hh * Bq) g_hbuf[idx] = 0.0f;
}

// ---------------- tiled f32x2 GEMM: C[m][n] = sum_k A[m][k]*W[z][n][k] + bias[z][n] --------
__global__ __launch_bounds__(256, 2) void k_gemm(const float* __restrict__ Wext, int K, int mode) {
    const float* A  = (mode == 0) ? g_xpad : g_h0;
    const float* Wb = (mode == 0) ? g_wpad : Wext;

    __shared__ __align__(16) float As[16][128];
    __shared__ __align__(16) float Ws[16][128];

    int tid = threadIdx.x;
    int m0 = blockIdx.x * 128, n0 = blockIdx.y * 128;
    int z  = blockIdx.z;

    const float* Ab = A  + (size_t)m0 * K;
    const float* Wz = Wb + ((size_t)z * Gg + n0) * K;

    u64 acc2[8][4];
#pragma unroll
    for (int i = 0; i < 8; i++)
#pragma unroll
        for (int j = 0; j < 4; j++) acc2[i][j] = 0ull;

    int tx = tid & 15, ty = tid >> 4;
    int lr = tid >> 2, lc = (tid & 3) * 4;

    for (int kt = 0; kt < K; kt += 16) {
        float4 a0 = *(const float4*)(Ab + (size_t)lr        * K + kt + lc);
        float4 a1 = *(const float4*)(Ab + (size_t)(lr + 64) * K + kt + lc);
        float4 w0 = *(const float4*)(Wz + (size_t)lr        * K + kt + lc);
        float4 w1 = *(const float4*)(Wz + (size_t)(lr + 64) * K + kt + lc);
        __syncthreads();
        As[lc + 0][lr] = a0.x; As[lc + 1][lr] = a0.y; As[lc + 2][lr] = a0.z; As[lc + 3][lr] = a0.w;
        As[lc + 0][lr + 64] = a1.x; As[lc + 1][lr + 64] = a1.y; As[lc + 2][lr + 64] = a1.z; As[lc + 3][lr + 64] = a1.w;
        Ws[lc + 0][lr] = w0.x; Ws[lc + 1][lr] = w0.y; Ws[lc + 2][lr] = w0.z; Ws[lc + 3][lr] = w0.w;
        Ws[lc + 0][lr + 64] = w1.x; Ws[lc + 1][lr + 64] = w1.y; Ws[lc + 2][lr + 64] = w1.z; Ws[lc + 3][lr + 64] = w1.w;
        __syncthreads();
#pragma unroll
        for (int k = 0; k < 16; k++) {
            float4 av0 = *(const float4*)&As[k][ty * 8];
            float4 av1 = *(const float4*)&As[k][ty * 8 + 4];
            ulonglong2 b0 = *(const ulonglong2*)&Ws[k][tx * 8];
            ulonglong2 b1 = *(const ulonglong2*)&Ws[k][tx * 8 + 4];
            float av[8];
            av[0]=av0.x; av[1]=av0.y; av[2]=av0.z; av[3]=av0.w;
            av[4]=av1.x; av[5]=av1.y; av[6]=av1.z; av[7]=av1.w;
#pragma unroll
            for (int i = 0; i < 8; i++) {
                u64 ad = dup2(av[i]);
                ffma2(acc2[i][0], ad, b0.x);
                ffma2(acc2[i][1], ad, b0.y);
                ffma2(acc2[i][2], ad, b1.x);
                ffma2(acc2[i][3], ad, b1.y);
            }
        }
    }

    float bb[8];
#pragma unroll
    for (int j = 0; j < 8; j++) bb[j] = g_bias[z * Gg + n0 + tx * 8 + j];

    float* Cb = g_ct + ((size_t)z * Mq + m0) * Gg + n0;
#pragma unroll
    for (int i = 0; i < 8; i++) {
        float2 q0 = unpk(acc2[i][0]), q1 = unpk(acc2[i][1]);
        float2 q2 = unpk(acc2[i][2]), q3 = unpk(acc2[i][3]);
        float4 v0, v1;
        v0.x = q0.x + bb[0]; v0.y = q0.y + bb[1]; v0.z = q1.x + bb[2]; v0.w = q1.y + bb[3];
        v1.x = q2.x + bb[4]; v1.y = q2.y + bb[5]; v1.z = q3.x + bb[6]; v1.w = q3.y + bb[7];
        *(float4*)&Cb[(size_t)(ty * 8 + i) * Gg + tx * 8]     = v0;
        *(float4*)&Cb[(size_t)(ty * 8 + i) * Gg + tx * 8 + 4] = v1;
    }
}

// ---------------- transpose g_ct [d][m=t*32+b][n] -> g_xp [d][t][n][b] ----------------
__global__ __launch_bounds__(256) void k_trans() {
    __shared__ float tile[32][33];
    int nc = blockIdx.x * 32, t = blockIdx.y, d = blockIdx.z;
    int tid = threadIdx.x;
    const float* src = g_ct + ((size_t)d * Mq + (size_t)t * Bq) * Gg;
#pragma unroll
    for (int i = 0; i < 4; i++) {
        int idx = tid + i * 256;
        int b = idx >> 5, n = idx & 31;
        tile[b][n] = src[(size_t)b * Gg + nc + n];
    }
    __syncthreads();
    float* dst = g_xp + (((size_t)d * Lq + t) * Gg + nc) * Bq;
#pragma unroll
    for (int i = 0; i < 4; i++) {
        int idx = tid + i * 256;
        int n = idx >> 5, b = idx & 31;
        dst[(size_t)n * Bq + b] = tile[b][n];
    }
}

// ---------------- per-direction software grid barrier (DBLK2 arrivals) ----------------
__device__ __forceinline__ void grid_bar_d(int d) {
    __syncthreads();
    if (threadIdx.x == 0) {
        unsigned gen = ((volatile unsigned*)g_gen)[d];
        __threadfence();                           // publish this block's h writes
        unsigned my = atomicAdd(&g_cnt[d], 1u);
        if (my == DBLK2 - 1) {
            atomicExch(&g_cnt[d], 0u);             // reset strictly before release
            __threadfence();
            atomicExch(&g_gen[d], gen + 1u);       // release
        } else {
            while (((volatile unsigned*)g_gen)[d] == gen) { __nanosleep(32); }
            __threadfence();                       // acquire before consuming peers' h
        }
    }
    __syncthreads();
}

// ---------------- persistent bidirectional LSTM recurrence (one launch per layer) -------
// 134 blocks x 384 threads, 217KB dynamic smem:
//   [0 .. 38400)              weights (resident all 700 steps)
//   [38400 .. +6400)          h chunk buffer A    [+6400 .. +12800) buffer B
//   [.. +REDF)                k-split reduction staging (u64 partial accs)
// 12 warps: warp w -> unit pair p=w%6 (units u0+2p, u0+2p+1), k-half hs=w/6.
// Each chunk's 8k-groups are interleaved between the two halves (hs picks parity).
// Partial f32x2 accumulators combined via smem; activation done by hs=0 warps.
__global__ __launch_bounds__(NTH) void k_rec(const float* __restrict__ whh, int mode) {
    extern __shared__ __align__(16) float sw[];
    float* shbuf[2] = { sw + SMEMW, sw + SMEMW + HCH * Bq };
    u64*   sred     = (u64*)(sw + SMEMW + 2 * HCH * Bq);

    const int warp = threadIdx.x >> 5, lane = threadIdx.x & 31;
    const int p  = warp % 6;                       // unit-pair index
    const int hs = warp / 6;                       // k-half (0: even 8k-groups, 1: odd)
    const int d   = (blockIdx.x >= DBLK2) ? 1 : 0;
    const int blk = blockIdx.x - d * DBLK2;
    const int u0  = blk * UPB;

    // ---- preload this block's 48 weight rows (UPB units x 4 gates x 800 floats) ----
    for (int idx = threadIdx.x; idx < UPB * 4 * (Hh / 4); idx += NTH) {
        int r = idx / (Hh / 4), i = idx - r * (Hh / 4);
        int lu = r >> 2, g = r & 3;
        int j = u0 + lu; if (j > Hh - 1) j = Hh - 1;
        ((float4*)(sw + (size_t)r * Hh))[i] =
            ((const float4*)(whh + ((size_t)d * Gg + (size_t)g * Hh + j) * Hh))[i];
    }
    __syncthreads();

    const int j0 = u0 + p * 2;                     // units j0, j0+1
    const bool act0 = (j0     < Hh);
    const bool act1 = (j0 + 1 < Hh);
    const int ja = act0 ? j0     : Hh - 1;
    const int jb = act1 ? j0 + 1 : Hh - 1;

    const float* wr[2][4];
#pragma unroll
    for (int i = 0; i < 2; i++)
#pragma unroll
        for (int g = 0; g < 4; g++)
            wr[i][g] = sw + (size_t)((p * 2 + i) * 4 + g) * Hh;

    unsigned sh_u32[2];
    sh_u32[0] = (unsigned)__cvta_generic_to_shared(shbuf[0]);
    sh_u32[1] = (unsigned)__cvta_generic_to_shared(shbuf[1]);

    float c0 = 0.0f, c1 = 0.0f;
    float* hout = mode ? g_h1 : g_h0;

    for (int t = 0; t < Lq; t++) {
        const int time = d ? (Lq - 1 - t) : t;
        const float4* hp4 = (const float4*)(g_hbuf +
                            ((size_t)(t & 1) * 2 + d) * ((size_t)Hh * Bq));
        float* hn = g_hbuf + ((size_t)((t + 1) & 1) * 2 + d) * ((size_t)Hh * Bq);
        const float* xpb = g_xp + ((size_t)d * Lq + time) * ((size_t)Gg * Bq);

        u64 acc[2][4];
        if (hs == 0) {
#pragma unroll
            for (int g = 0; g < 4; g++) {
                acc[0][g] = pklo(__ldcs(&xpb[((size_t)g * Hh + ja) * Bq + lane]));
                acc[1][g] = pklo(__ldcs(&xpb[((size_t)g * Hh + jb) * Bq + lane]));
            }
        } else {
#pragma unroll
            for (int g = 0; g < 4; g++) { acc[0][g] = 0ull; acc[1][g] = 0ull; }
        }

        // ---- prefetch chunks 0 and 1 ----
#pragma unroll
        for (int pc = 0; pc < 2; pc++) {
            const float4* src = hp4 + pc * HCHF4;
            for (int idx = threadIdx.x; idx < HCHF4; idx += NTH)
                CP_ASYNC16(sh_u32[pc] + idx * 16, src + idx);
            CP_COMMIT();
        }

        // ---- 4 chunks: compute c while c+1 in flight; prefetch c+2 after use ----
#pragma unroll
        for (int ch = 0; ch < 4; ch++) {
            if (ch < 3) { CP_WAIT(1); } else { CP_WAIT(0); }
            __syncthreads();                       // chunk ch resident for all threads

            const float* buf = shbuf[ch & 1];
            const int kofs = ch * HCH;
            const ulonglong2* b2 = (const ulonglong2*)buf;
            // this warp takes 8k-groups of its parity: kk = hs*8, hs*8+16, ...
#pragma unroll 2
            for (int kk = hs * 8; kk < HCH; kk += 16) {
                ulonglong2 hA = b2[(kk >> 2)       * Bq + lane];   // h[k..k+3]
                ulonglong2 hB = b2[((kk >> 2) + 1) * Bq + lane];   // h[k+4..k+7]
#pragma unroll
                for (int i = 0; i < 2; i++)
#pragma unroll
                    for (int g = 0; g < 4; g++) {
                        const float* w = wr[i][g] + kofs + kk;
                        ulonglong2 wA = *(const ulonglong2*)(w);      // uniform LDS.128
                        ulonglong2 wB = *(const ulonglong2*)(w + 4);
                        ffma2(acc[i][g], hA.x, wA.x);
                        ffma2(acc[i][g], hA.y, wA.y);
                        ffma2(acc[i][g], hB.x, wB.x);
                        ffma2(acc[i][g], hB.y, wB.y);
                    }
            }

            if (ch < 2) {
                __syncthreads();                   // all done reading buf before overwrite
                const float4* src = hp4 + (ch + 2) * HCHF4;
                for (int idx = threadIdx.x; idx < HCHF4; idx += NTH)
                    CP_ASYNC16(sh_u32[ch & 1] + idx * 16, src + idx);
                CP_COMMIT();
            }
        }

        // ---- combine k-halves: hs=1 stages partials, hs=0 reduces + activates ----
        if (hs == 1) {
#pragma unroll
            for (int i = 0; i < 2; i++)
#pragma unroll
                for (int g = 0; g < 4; g++)
                    sred[(size_t)(((p * 2 + i) * 4 + g) * 32) + lane] = acc[i][g];
        }
        __syncthreads();

        if (hs == 0) {
#pragma unroll
            for (int i = 0; i < 2; i++) {
                float2 pr[4];
#pragma unroll
                for (int g = 0; g < 4; g++) {
                    float2 a = unpk(acc[i][g]);
                    float2 b = unpk(sred[(size_t)(((p * 2 + i) * 4 + g) * 32) + lane]);
                    pr[g].x = a.x + b.x; pr[g].y = a.y + b.y;
                }
                float ai = pr[0].x + pr[0].y, af = pr[1].x + pr[1].y;
                float ag = pr[2].x + pr[2].y, ao = pr[3].x + pr[3].y;
                float si = 1.0f / (1.0f + expf(-ai));
                float sf = 1.0f / (1.0f + expf(-af));
                float so = 1.0f / (1.0f + expf(-ao));
                float tg = tanhf(ag);
                float cprev = i ? c1 : c0;
                float cn = sf * cprev + si * tg;
                float hv = so * tanhf(cn);
                bool act = i ? act1 : act0;
                int  j   = i ? jb : ja;
                if (act) {
                    if (i) c1 = cn; else c0 = cn;
                    hn[((size_t)(j >> 2) * Bq + lane) * 4 + (j & 3)] = hv;
                    hout[((size_t)time * Bq + lane) * H2 + (size_t)d * Hh + j] = hv;
                }
            }
        }
        grid_bar_d(d);
    }
}

// ---------------- logits = h1 @ w_lin^T + b_lin ----------------
__global__ __launch_bounds__(256) void k_logits(const float* __restrict__ wlin,
                                                const float* __restrict__ blin) {
    __shared__ float sh[H2];
    int t = blockIdx.x, b = blockIdx.y;
    const float* hrow = g_h1 + ((size_t)t * Bq + b) * H2;
    for (int i = threadIdx.x; i < H2; i += 256) sh[i] = hrow[i];
    __syncthreads();
    int warp = threadIdx.x >> 5, lane = threadIdx.x & 31;
    for (int n = warp; n < 20; n += 8) {
        float acc = 0.0f;
        const float* wr = wlin + (size_t)n * H2;
        for (int k = lane; k < H2; k += 32) acc = fmaf(sh[k], wr[k], acc);
#pragma unroll
        for (int off = 16; off; off >>= 1) acc += __shfl_xor_sync(0xffffffffu, acc, off);
        if (lane == 0) g_logits[((size_t)t * Bq + b) * 20 + n] = acc + blin[n];
    }
}

// ---------------- softmax over BATCH axis + alphabet angularization ----------------
__global__ void k_angles(const float* __restrict__ alpha) {
    int l = blockIdx.x, lane = threadIdx.x;  // 32 threads, lane = batch
    const float* row = g_logits + ((size_t)l * Bq + lane) * 20;
    float p[20];
#pragma unroll
    for (int n = 0; n < 20; n++) p[n] = row[n];
#pragma unroll
    for (int n = 0; n < 20; n++) {
        float v = p[n], mx = v;
        for (int off = 16; off; off >>= 1) mx = fmaxf(mx, __shfl_xor_sync(0xffffffffu, mx, off));
        float e = expf(v - mx), s = e;
        for (int off = 16; off; off >>= 1) s += __shfl_xor_sync(0xffffffffu, s, off);
        p[n] = e / s;                         // softmax over batch dim (axis=1 of [L,B,20])
    }
#pragma unroll
    for (int jj = 0; jj < 3; jj++) {
        float ss = 0.0f, cc = 0.0f;
        for (int n = 0; n < 20; n++) {
            float al = alpha[n * 3 + jj];
            ss = fmaf(p[n], sinf(al), ss);
            cc = fmaf(p[n], cosf(al), cc);
        }
        g_ang[((size_t)l * Bq + lane) * 3 + jj] = atan2f(ss, cc);
    }
}

// ---------------- NeRF backbone extension: sequential scan, lane = scan column -------
__global__ void k_nerf(float* __restrict__ out) {
    int lane = threadIdx.x;
    float ax = 0.f,   ay = 0.f,   az = 0.f;
    float bx = 100.f, by = 0.f,   bz = 0.f;
    float cx = 200.f, cy = 100.f, cz = 0.f;
    float d0c[3], rstc[3];
#pragma unroll
    for (int jj = 0; jj < 3; jj++) {
        d0c[jj]  = -c_bl[jj] * cosf(c_ba[jj]);
        rstc[jj] =  c_bl[jj] * sinf(c_ba[jj]);
    }

    float nphi = g_ang[lane];
    for (int s = 0; s < 2100; s++) {
        float phi = nphi;
        if (s + 1 < 2100) nphi = g_ang[(size_t)(s + 1) * Bq + lane];
        int jj = s - (s / 3) * 3;
        float d0 = d0c[jj];
        float sp, cp;
        sincosf(phi, &sp, &cp);
        float d1 = rstc[jj] * cp;
        float d2 = rstc[jj] * sp;

        float ux = cx - bx, uy = cy - by, uz = cz - bz;
        float inv = 1.0f / (sqrtf(ux * ux + uy * uy + uz * uz) + 1e-12f);
        float bcx = ux * inv, bcy = uy * inv, bcz = uz * inv;

        float vx = bx - ax, vy = by - ay, vz = bz - az;
        float nx = vy * bcz - vz * bcy;
        float ny = vz * bcx - vx * bcz;
        float nz = vx * bcy - vy * bcx;
        float inv2 = 1.0f / (sqrtf(nx * nx + ny * ny + nz * nz) + 1e-12f);
        nx *= inv2; ny *= inv2; nz *= inv2;

        float mx = ny * bcz - nz * bcy;
        float my = nz * bcx - nx * bcz;
        float mz = nx * bcy - ny * bcx;

        float Dx = cx + d0 * bcx + d1 * mx + d2 * nx;
        float Dy = cy + d0 * bcy + d1 * my + d2 * ny;
        float Dz = cz + d0 * bcz + d1 * mz + d2 * nz;

        size_t o = ((size_t)s * Bq + lane) * 3;
        out[o] = Dx; out[o + 1] = Dy; out[o + 2] = Dz;

        ax = bx; ay = by; az = bz;
        bx = cx; by = cy; bz = cz;
        cx = Dx; cy = Dy; cz = Dz;
    }
}

// ---------------- host orchestration ----------------
extern "C" void kernel_launch(void* const* d_in, const int* in_sizes, int n_in,
                              void* d_out, int out_size) {
    const float* x     = (const float*)d_in[0];
    const float* wih0  = (const float*)d_in[1];
    const float* whh0  = (const float*)d_in[2];
    const float* bih0  = (const float*)d_in[3];
    const float* bhh0  = (const float*)d_in[4];
    const float* wih1  = (const float*)d_in[5];
    const float* whh1  = (const float*)d_in[6];
    const float* bih1  = (const float*)d_in[7];
    const float* bhh1  = (const float*)d_in[8];
    const float* wlin  = (const float*)d_in[9];
    const float* blin  = (const float*)d_in[10];
    const float* alpha = (const float*)d_in[11];
    float* out = (float*)d_out;

    // allow 217KB dynamic smem for the persistent recurrence kernel (idempotent)
    cudaFuncSetAttribute(k_rec, cudaFuncAttributeMaxDynamicSharedMemorySize, SMEMB);

    // ---- layer 0 ----
    k_padx<<<(Mq * KP + 255) / 256, 256>>>(x);
    k_padw<<<(2 * Gg * KP + 255) / 256, 256>>>(wih0);
    k_bias<<<(2 * Gg + 255) / 256, 256>>>(bih0, bhh0);
    k_gemm<<<dim3(Mq / 128, Gg / 128, 2), 256>>>(nullptr, KP, 0);
    k_trans<<<dim3(Gg / 32, Lq, 2), 256>>>();
    k_zero<<<(2 * 2 * Hh * Bq + 255) / 256, 256>>>();
    k_rec<<<RBLK2, NTH, SMEMB>>>(whh0, 0);

    // ---- layer 1 ----
    k_bias<<<(2 * Gg + 255) / 256, 256>>>(bih1, bhh1);
    k_gemm<<<dim3(Mq / 128, Gg / 128, 2), 256>>>(wih1, H2, 1);
    k_trans<<<dim3(Gg / 32, Lq, 2), 256>>>();
    k_zero<<<(2 * 2 * Hh * Bq + 255) / 256, 256>>>();
    k_rec<<<RBLK2, NTH, SMEMB>>>(whh1, 1);

    // ---- head + geometry ----
    k_logits<<<dim3(Lq, Bq), 256>>>(wlin, blin);
    k_angles<<<Lq, 32>>>(alpha);
    k_nerf<<<1, 32>>>(out);
}

// round 16
// speedup vs baseline: 5.1328x; 1.1562x over previous
#include <cuda_runtime.h>
#include <math.h>

// Problem constants
#define Lq   700
#define Bq   32
#define DIN  41
#define Hh   800
#define Gg   3200      // 4*H
#define H2   1600      // 2*H
#define Mq   22400     // L*B
#define KP   48        // padded K for layer-0 input projection

// persistent recurrence: 134 blocks (1/SM), split by direction
#define RBLK 134
#define DBLK 67        // blocks per direction; 67*12 = 804 >= 800 unit slots
#define UPB  12        // units per block (48 gate-rows)
#define NTH3 128       // 4 warps = 4 k-quarters of 200 k each
#define SW_HOFF 38400  // float offset of h buffers (w = 800*48 floats)
#define SMEMB3 ((38400 + 4*2*50*32) * 4)   // 204800 bytes

// ---------------- device scratch (static; no runtime allocation) ----------------
__device__ __align__(16) float g_xp  [(size_t)2*Lq*Gg*Bq];  // gate preacts [dir][t][n][b]
__device__ __align__(16) float g_ct  [(size_t)2*Mq*Gg];     // GEMM out [dir][m][n]
__device__ __align__(16) float g_h0  [(size_t)Mq*H2];       // layer-0 hidden [t][b][1600]
__device__ __align__(16) float g_h1  [(size_t)Mq*H2];       // layer-1 hidden
__device__ __align__(16) float g_hbuf[2*2*Hh*Bq];           // ping-pong h [buf][dir][j][b]
__device__ __align__(16) float g_xpad[(size_t)Mq*KP];       // padded x  [m=t*32+b][48]
__device__ __align__(16) float g_wpad[(size_t)2*Gg*KP];     // padded w_ih_l0
__device__ float g_bias[2*Gg];
__device__ float g_logits[(size_t)Mq*20];
__device__ float g_ang[(size_t)Lq*Bq*3];    // angles in NATURAL [l][b][jj] order; NeRF reads
                                            // this flat as [2100][32] == reference's reshape.
__device__ unsigned g_gen[2];    // per-direction barrier generation (monotonic)
__device__ unsigned g_cnt[2];    // per-direction arrival counters

__constant__ float c_bl[3] = {145.801f, 152.326f, 132.868f};
__constant__ float c_ba[3] = {2.124f, 1.941f, 2.028f};

typedef unsigned long long u64;

// ---------------- f32x2 helpers (numerics cross-validated R8<->R9) ----------------
__device__ __forceinline__ void ffma2(u64 &c, u64 a, u64 b) {
    asm("fma.rn.f32x2 %0, %1, %2, %0;" : "+l"(c) : "l"(a), "l"(b));
}
__device__ __forceinline__ u64 dup2(float x) {
    u64 r; unsigned u = __float_as_uint(x);
    asm("mov.b64 %0, {%1, %1};" : "=l"(r) : "r"(u));
    return r;
}
__device__ __forceinline__ float2 unpk(u64 v) {
    unsigned lo, hi;
    asm("mov.b64 {%0, %1}, %2;" : "=r"(lo), "=r"(hi) : "l"(v));
    float2 f; f.x = __uint_as_float(lo); f.y = __uint_as_float(hi);
    return f;
}

// cp.async: 16B global->shared, L2-only (.cg) — correct coherence for cross-SM h
#define CP_ASYNC16(dst_u32, src_ptr) \
    asm volatile("cp.async.cg.shared.global [%0], [%1], 16;" :: "r"(dst_u32), "l"(src_ptr))
#define CP_COMMIT() asm volatile("cp.async.commit_group;")
#define CP_WAIT(n)  asm volatile("cp.async.wait_group %0;" :: "n"(n))

// ---------------- small prep kernels ----------------
__global__ void k_padx(const float* __restrict__ x) {
    int idx = blockIdx.x * 256 + threadIdx.x;
    if (idx >= Mq * KP) return;
    int m = idx / KP, k = idx - m * KP;
    int b = m & 31, t = m >> 5;                       // m = t*32 + b
    g_xpad[idx] = (k < DIN) ? x[((size_t)b * Lq + t) * DIN + k] : 0.0f;   // x is [B][L][Din]
}

__global__ void k_padw(const float* __restrict__ w) {
    int idx = blockIdx.x * 256 + threadIdx.x;
    if (idx >= 2 * Gg * KP) return;
    int r = idx / KP, k = idx - r * KP;
    g_wpad[idx] = (k < DIN) ? w[(size_t)r * DIN + k] : 0.0f;
}

__global__ void k_bias(const float* __restrict__ bih, const float* __restrict__ bhh) {
    int idx = blockIdx.x * 256 + threadIdx.x;
    if (idx < 2 * Gg) g_bias[idx] = bih[idx] + bhh[idx];
}

__global__ void k_zero() {
    int idx = blockIdx.x * 256 + threadIdx.x;
    if (idx < 2 * 2 * Hh * Bq) g_hbuf[idx] = 0.0f;
}

// ---------------- tiled f32x2 GEMM: C[m][n] = sum_k A[m][k]*W[z][n][k] + bias[z][n] --------
__global__ __launch_bounds__(256, 2) void k_gemm(const float* __restrict__ Wext, int K, int mode) {
    const float* A  = (mode == 0) ? g_xpad : g_h0;
    const float* Wb = (mode == 0) ? g_wpad : Wext;

    __shared__ __align__(16) float As[16][128];
    __shared__ __align__(16) float Ws[16][128];

    int tid = threadIdx.x;
    int m0 = blockIdx.x * 128, n0 = blockIdx.y * 128;
    int z  = blockIdx.z;

    const float* Ab = A  + (size_t)m0 * K;
    const float* Wz = Wb + ((size_t)z * Gg + n0) * K;

    u64 acc2[8][4];
#pragma unroll
    for (int i = 0; i < 8; i++)
#pragma unroll
        for (int j = 0; j < 4; j++) acc2[i][j] = 0ull;

    int tx = tid & 15, ty = tid >> 4;
    int lr = tid >> 2, lc = (tid & 3) * 4;

    for (int kt = 0; kt < K; kt += 16) {
        float4 a0 = *(const float4*)(Ab + (size_t)lr        * K + kt + lc);
        float4 a1 = *(const float4*)(Ab + (size_t)(lr + 64) * K + kt + lc);
        float4 w0 = *(const float4*)(Wz + (size_t)lr        * K + kt + lc);
        float4 w1 = *(const float4*)(Wz + (size_t)(lr + 64) * K + kt + lc);
        __syncthreads();
        As[lc + 0][lr] = a0.x; As[lc + 1][lr] = a0.y; As[lc + 2][lr] = a0.z; As[lc + 3][lr] = a0.w;
        As[lc + 0][lr + 64] = a1.x; As[lc + 1][lr + 64] = a1.y; As[lc + 2][lr + 64] = a1.z; As[lc + 3][lr + 64] = a1.w;
        Ws[lc + 0][lr] = w0.x; Ws[lc + 1][lr] = w0.y; Ws[lc + 2][lr] = w0.z; Ws[lc + 3][lr] = w0.w;
        Ws[lc + 0][lr + 64] = w1.x; Ws[lc + 1][lr + 64] = w1.y; Ws[lc + 2][lr + 64] = w1.z; Ws[lc + 3][lr + 64] = w1.w;
        __syncthreads();
#pragma unroll
        for (int k = 0; k < 16; k++) {
            float4 av0 = *(const float4*)&As[k][ty * 8];
            float4 av1 = *(const float4*)&As[k][ty * 8 + 4];
            ulonglong2 b0 = *(const ulonglong2*)&Ws[k][tx * 8];
            ulonglong2 b1 = *(const ulonglong2*)&Ws[k][tx * 8 + 4];
            float av[8];
            av[0]=av0.x; av[1]=av0.y; av[2]=av0.z; av[3]=av0.w;
            av[4]=av1.x; av[5]=av1.y; av[6]=av1.z; av[7]=av1.w;
#pragma unroll
            for (int i = 0; i < 8; i++) {
                u64 ad = dup2(av[i]);
                ffma2(acc2[i][0], ad, b0.x);
                ffma2(acc2[i][1], ad, b0.y);
                ffma2(acc2[i][2], ad, b1.x);
                ffma2(acc2[i][3], ad, b1.y);
            }
        }
    }

    float bb[8];
#pragma unroll
    for (int j = 0; j < 8; j++) bb[j] = g_bias[z * Gg + n0 + tx * 8 + j];

    float* Cb = g_ct + ((size_t)z * Mq + m0) * Gg + n0;
#pragma unroll
    for (int i = 0; i < 8; i++) {
        float2 q0 = unpk(acc2[i][0]), q1 = unpk(acc2[i][1]);
        float2 q2 = unpk(acc2[i][2]), q3 = unpk(acc2[i][3]);
        float4 v0, v1;
        v0.x = q0.x + bb[0]; v0.y = q0.y + bb[1]; v0.z = q1.x + bb[2]; v0.w = q1.y + bb[3];
        v1.x = q2.x + bb[4]; v1.y = q2.y + bb[5]; v1.z = q3.x + bb[6]; v1.w = q3.y + bb[7];
        *(float4*)&Cb[(size_t)(ty * 8 + i) * Gg + tx * 8]     = v0;
        *(float4*)&Cb[(size_t)(ty * 8 + i) * Gg + tx * 8 + 4] = v1;
    }
}

// ---------------- transpose g_ct [d][m=t*32+b][n] -> g_xp [d][t][n][b] ----------------
__global__ __launch_bounds__(256) void k_trans() {
    __shared__ float tile[32][33];
    int nc = blockIdx.x * 32, t = blockIdx.y, d = blockIdx.z;
    int tid = threadIdx.x;
    const float* src = g_ct + ((size_t)d * Mq + (size_t)t * Bq) * Gg;
#pragma unroll
    for (int i = 0; i < 4; i++) {
        int idx = tid + i * 256;
        int b = idx >> 5, n = idx & 31;
        tile[b][n] = src[(size_t)b * Gg + nc + n];
    }
    __syncthreads();
    float* dst = g_xp + (((size_t)d * Lq + t) * Gg + nc) * Bq;
#pragma unroll
    for (int i = 0; i < 4; i++) {
        int idx = tid + i * 256;
        int n = idx >> 5, b = idx & 31;
        dst[(size_t)n * Bq + b] = tile[b][n];
    }
}

// ---------------- per-direction software grid barrier (DBLK arrivals) ----------------
__device__ __forceinline__ void grid_bar_d(int d) {
    __syncthreads();
    if (threadIdx.x == 0) {
        unsigned gen = ((volatile unsigned*)g_gen)[d];
        __threadfence();                           // publish this block's h writes
        unsigned my = atomicAdd(&g_cnt[d], 1u);
        if (my == DBLK - 1) {
            atomicExch(&g_cnt[d], 0u);             // reset strictly before release
            __threadfence();
            atomicExch(&g_gen[d], gen + 1u);       // release
        } else {
            while (((volatile unsigned*)g_gen)[d] == gen) { __nanosleep(32); }
            __threadfence();                       // acquire before consuming peers' h
        }
    }
    __syncthreads();
}

// ---------------- persistent bidirectional LSTM recurrence (one launch per layer) -------
// 134 blocks x 128 threads (4 warps), 204.8KB smem:
//   [0 .. 38400)   weights TRANSPOSED [k][48] (col = local_unit*4 + gate), resident 700 steps
//   [38400 .. )    per-warp h double buffers: warp w at +w*3200 (2 x 50k x 32b chunks)
//                  (aliased by the k-split reduction stage after the FMA loop)
// Warp = one k-quarter (200 k). Lane grid 4 b-hat x 8 n-hat; thread micro-tile:
// 8 batch (4 f32x2 pairs) x 6 cols -> 24 u64 accs, 48 MACs / 56 delivered bytes per k.
// h staged via warp-private cp.async.cg (no block syncs in mainloop).
__global__ __launch_bounds__(NTH3) void k_rec(const float* __restrict__ whh, int mode) {
    extern __shared__ __align__(16) float sw[];
    const int tid  = threadIdx.x;
    const int warp = tid >> 5, lane = tid & 31;
    const int d   = (blockIdx.x >= DBLK) ? 1 : 0;
    const int blk = blockIdx.x - d * DBLK;
    const int u0  = blk * UPB;

    // ---- preload weights transposed: sw[k*48 + col] ----
    for (int r = 0; r < 48; r++) {
        int lu = r >> 2, g = r & 3;
        int j = u0 + lu; if (j > Hh - 1) j = Hh - 1;
        const float* src = whh + ((size_t)d * Gg + (size_t)g * Hh + j) * Hh;
        for (int k = tid; k < Hh; k += NTH3)
            sw[(size_t)k * 48 + r] = src[k];
    }
    __syncthreads();

    const int bh = (lane >> 3) * 8;      // batch base: 0,8,16,24
    const int nh = (lane & 7) * 6;       // col base: 0..42

    float* hb0 = sw + SW_HOFF + warp * 3200;
    float* hb1 = hb0 + 1600;
    unsigned hbu[2] = { (unsigned)__cvta_generic_to_shared(hb0),
                        (unsigned)__cvta_generic_to_shared(hb1) };
    const float* hbp[2] = { hb0, hb1 };
    u64* sred = (u64*)(sw + SW_HOFF);    // aliases h buffers (dead after FMA loop)

    float cst[3] = {0.f, 0.f, 0.f};
    float* hout = mode ? g_h1 : g_h0;

    for (int t = 0; t < Lq; t++) {
        const int time = d ? (Lq - 1 - t) : t;
        const float* hp = g_hbuf + ((size_t)(t & 1) * 2 + d) * ((size_t)Hh * Bq);
        float*       hn = g_hbuf + ((size_t)((t + 1) & 1) * 2 + d) * ((size_t)Hh * Bq);
        const float* xpb = g_xp + ((size_t)d * Lq + time) * ((size_t)Gg * Bq);

        // issue chunks 0,1 of this warp's k-quarter (warp-private buffers)
        const float4* hq = (const float4*)(hp + warp * 6400);
#pragma unroll
        for (int c = 0; c < 2; c++) {
            const float4* s = hq + c * 400;
            for (int ci = lane; ci < 400; ci += 32)
                CP_ASYNC16(hbu[c] + ci * 16, s + ci);
            CP_COMMIT();
        }

        // xp prefetch for activation (3 units x 4 gates) — consumed after FMA loop
        float xpr[3][4];
#pragma unroll
        for (int ii = 0; ii < 3; ii++) {
            int j = u0 + warp + 4 * ii; if (j > Hh - 1) j = Hh - 1;
#pragma unroll
            for (int g = 0; g < 4; g++)
                xpr[ii][g] = __ldcs(xpb + ((size_t)g * Hh + j) * Bq + lane);
        }

        u64 acc[4][6];
#pragma unroll
        for (int bp = 0; bp < 4; bp++)
#pragma unroll
            for (int nn = 0; nn < 6; nn++) acc[bp][nn] = 0ull;

#pragma unroll
        for (int ch = 0; ch < 4; ch++) {
            if (ch < 3) { CP_WAIT(1); } else { CP_WAIT(0); }
            const float* buf = hbp[ch & 1];
            const float* wbase = sw + (size_t)(warp * 200 + ch * 50) * 48 + nh;
#pragma unroll 2
            for (int kk = 0; kk < 50; kk++) {
                ulonglong2 hA = *(const ulonglong2*)(buf + kk * 32 + bh);      // b-pairs 0,1
                ulonglong2 hB = *(const ulonglong2*)(buf + kk * 32 + bh + 4);  // b-pairs 2,3
                const float* wk = wbase + (size_t)kk * 48;
                u64 w01 = *(const u64*)(wk);
                u64 w23 = *(const u64*)(wk + 2);
                u64 w45 = *(const u64*)(wk + 4);
                float2 wa = unpk(w01), wb = unpk(w23), wc = unpk(w45);
                u64 wd0 = dup2(wa.x), wd1 = dup2(wa.y);
                u64 wd2 = dup2(wb.x), wd3 = dup2(wb.y);
                u64 wd4 = dup2(wc.x), wd5 = dup2(wc.y);
                u64 hv4[4] = { hA.x, hA.y, hB.x, hB.y };
#pragma unroll
                for (int bp = 0; bp < 4; bp++) {
                    ffma2(acc[bp][0], hv4[bp], wd0);
                    ffma2(acc[bp][1], hv4[bp], wd1);
                    ffma2(acc[bp][2], hv4[bp], wd2);
                    ffma2(acc[bp][3], hv4[bp], wd3);
                    ffma2(acc[bp][4], hv4[bp], wd4);
                    ffma2(acc[bp][5], hv4[bp], wd5);
                }
            }
            if (ch < 2) {
                const float4* s = hq + (ch + 2) * 400;
                for (int ci = lane; ci < 400; ci += 32)
                    CP_ASYNC16(hbu[ch & 1] + ci * 16, s + ci);
                CP_COMMIT();
            }
        }

        // ---- k-split reduction: stage partials (17-stride padded, aliases h bufs) ----
        __syncthreads();                 // all warps done reading buffers before alias write
#pragma unroll
        for (int nn = 0; nn < 6; nn++)
#pragma unroll
            for (int bp = 0; bp < 4; bp++)
                sred[(size_t)(warp * 48 + nh + nn) * 17 + (bh >> 1) + bp] = acc[bp][nn];
        __syncthreads();

        // ---- reduce + activation: thread handles (unit = warp+4*ii, batch = lane) ----
#pragma unroll
        for (int ii = 0; ii < 3; ii++) {
            int lu = warp + 4 * ii;
            int j  = u0 + lu;
            float gt[4];
#pragma unroll
            for (int g = 0; g < 4; g++) {
                int col = lu * 4 + g;
                float s0 = 0.f;
#pragma unroll
                for (int ks = 0; ks < 4; ks++) {
                    float2 f = unpk(sred[(size_t)(ks * 48 + col) * 17 + (lane >> 1)]);
                    s0 += (lane & 1) ? f.y : f.x;
                }
                gt[g] = s0 + xpr[ii][g];
            }
            float si = 1.0f / (1.0f + expf(-gt[0]));
            float sf = 1.0f / (1.0f + expf(-gt[1]));
            float tg = tanhf(gt[2]);
            float so = 1.0f / (1.0f + expf(-gt[3]));
            float cn = sf * cst[ii] + si * tg;
            float hv = so * tanhf(cn);
            if (j < Hh) {
                cst[ii] = cn;
                hn[(size_t)j * Bq + lane] = hv;
                hout[((size_t)time * Bq + lane) * H2 + (size_t)d * Hh + j] = hv;
            }
        }
        grid_bar_d(d);
    }
}

// ---------------- logits = h1 @ w_lin^T + b_lin ----------------
__global__ __launch_bounds__(256) void k_logits(const float* __restrict__ wlin,
                                                const float* __restrict__ blin) {
    __shared__ float sh[H2];
    int t = blockIdx.x, b = blockIdx.y;
    const float* hrow = g_h1 + ((size_t)t * Bq + b) * H2;
    for (int i = threadIdx.x; i < H2; i += 256) sh[i] = hrow[i];
    __syncthreads();
    int warp = threadIdx.x >> 5, lane = threadIdx.x & 31;
    for (int n = warp; n < 20; n += 8) {
        float acc = 0.0f;
        const float* wr = wlin + (size_t)n * H2;
        for (int k = lane; k < H2; k += 32) acc = fmaf(sh[k], wr[k], acc);
#pragma unroll
        for (int off = 16; off; off >>= 1) acc += __shfl_xor_sync(0xffffffffu, acc, off);
        if (lane == 0) g_logits[((size_t)t * Bq + b) * 20 + n] = acc + blin[n];
    }
}

// ---------------- softmax over BATCH axis + alphabet angularization ----------------
__global__ void k_angles(const float* __restrict__ alpha) {
    int l = blockIdx.x, lane = threadIdx.x;  // 32 threads, lane = batch
    const float* row = g_logits + ((size_t)l * Bq + lane) * 20;
    float p[20];
#pragma unroll
    for (int n = 0; n < 20; n++) p[n] = row[n];
#pragma unroll
    for (int n = 0; n < 20; n++) {
        float v = p[n], mx = v;
        for (int off = 16; off; off >>= 1) mx = fmaxf(mx, __shfl_xor_sync(0xffffffffu, mx, off));
        float e = expf(v - mx), s = e;
        for (int off = 16; off; off >>= 1) s += __shfl_xor_sync(0xffffffffu, s, off);
        p[n] = e / s;                         // softmax over batch dim (axis=1 of [L,B,20])
    }
#pragma unroll
    for (int jj = 0; jj < 3; jj++) {
        float ss = 0.0f, cc = 0.0f;
        for (int n = 0; n < 20; n++) {
            float al = alpha[n * 3 + jj];
            ss = fmaf(p[n], sinf(al), ss);
            cc = fmaf(p[n], cosf(al), cc);
        }
        g_ang[((size_t)l * Bq + lane) * 3 + jj] = atan2f(ss, cc);
    }
}

// ---------------- NeRF backbone extension: sequential scan, lane = scan column -------
__global__ void k_nerf(float* __restrict__ out) {
    int lane = threadIdx.x;
    float ax = 0.f,   ay = 0.f,   az = 0.f;
    float bx = 100.f, by = 0.f,   bz = 0.f;
    float cx = 200.f, cy = 100.f, cz = 0.f;
    float d0c[3], rstc[3];
#pragma unroll
    for (int jj = 0; jj < 3; jj++) {
        d0c[jj]  = -c_bl[jj] * cosf(c_ba[jj]);
        rstc[jj] =  c_bl[jj] * sinf(c_ba[jj]);
    }

    float nphi = g_ang[lane];
    for (int s = 0; s < 2100; s++) {
        float phi = nphi;
        if (s + 1 < 2100) nphi = g_ang[(size_t)(s + 1) * Bq + lane];
        int jj = s - (s / 3) * 3;
        float d0 = d0c[jj];
        float sp, cp;
        sincosf(phi, &sp, &cp);
        float d1 = rstc[jj] * cp;
        float d2 = rstc[jj] * sp;

        float ux = cx - bx, uy = cy - by, uz = cz - bz;
        float inv = 1.0f / (sqrtf(ux * ux + uy * uy + uz * uz) + 1e-12f);
        float bcx = ux * inv, bcy = uy * inv, bcz = uz * inv;

        float vx = bx - ax, vy = by - ay, vz = bz - az;
        float nx = vy * bcz - vz * bcy;
        float ny = vz * bcx - vx * bcz;
        float nz = vx * bcy - vy * bcx;
        float inv2 = 1.0f / (sqrtf(nx * nx + ny * ny + nz * nz) + 1e-12f);
        nx *= inv2; ny *= inv2; nz *= inv2;

        float mx = ny * bcz - nz * bcy;
        float my = nz * bcx - nx * bcz;
        float mz = nx * bcy - ny * bcx;

        float Dx = cx + d0 * bcx + d1 * mx + d2 * nx;
        float Dy = cy + d0 * bcy + d1 * my + d2 * ny;
        float Dz = cz + d0 * bcz + d1 * mz + d2 * nz;

        size_t o = ((size_t)s * Bq + lane) * 3;
        out[o] = Dx; out[o + 1] = Dy; out[o + 2] = Dz;

        ax = bx; ay = by; az = bz;
        bx = cx; by = cy; bz = cz;
        cx = Dx; cy = Dy; cz = Dz;
    }
}

// ---------------- host orchestration ----------------
extern "C" void kernel_launch(void* const* d_in, const int* in_sizes, int n_in,
                              void* d_out, int out_size) {
    const float* x     = (const float*)d_in[0];
    const float* wih0  = (const float*)d_in[1];
    const float* whh0  = (const float*)d_in[2];
    const float* bih0  = (const float*)d_in[3];
    const float* bhh0  = (const float*)d_in[4];
    const float* wih1  = (const float*)d_in[5];
    const float* whh1  = (const float*)d_in[6];
    const float* bih1  = (const float*)d_in[7];
    const float* bhh1  = (const float*)d_in[8];
    const float* wlin  = (const float*)d_in[9];
    const float* blin  = (const float*)d_in[10];
    const float* alpha = (const float*)d_in[11];
    float* out = (float*)d_out;

    // allow 204.8KB dynamic smem for the persistent recurrence kernel (idempotent)
    cudaFuncSetAttribute(k_rec, cudaFuncAttributeMaxDynamicSharedMemorySize, SMEMB3);

    // ---- layer 0 ----
    k_padx<<<(Mq * KP + 255) / 256, 256>>>(x);
    k_padw<<<(2 * Gg * KP + 255) / 256, 256>>>(wih0);
    k_bias<<<(2 * Gg + 255) / 256, 256>>>(bih0, bhh0);
    k_gemm<<<dim3(Mq / 128, Gg / 128, 2), 256>>>(nullptr, KP, 0);
    k_trans<<<dim3(Gg / 32, Lq, 2), 256>>>();
    k_zero<<<(2 * 2 * Hh * Bq + 255) / 256, 256>>>();
    k_rec<<<RBLK, NTH3, SMEMB3>>>(whh0, 0);

    // ---- layer 1 ----
    k_bias<<<(2 * Gg + 255) / 256, 256>>>(bih1, bhh1);
    k_gemm<<<dim3(Mq / 128, Gg / 128, 2), 256>>>(wih1, H2, 1);
    k_trans<<<dim3(Gg / 32, Lq, 2), 256>>>();
    k_zero<<<(2 * 2 * Hh * Bq + 255) / 256, 256>>>();
    k_rec<<<RBLK, NTH3, SMEMB3>>>(whh1, 1);

    // ---- head + geometry ----
    k_logits<<<dim3(Lq, Bq), 256>>>(wlin, blin);
    k_angles<<<Lq, 32>>>(alpha);
    k_nerf<<<1, 32>>>(out);
}